// round 13
// baseline (speedup 1.0000x reference)
#include <cuda_runtime.h>
#include <cuda_fp16.h>
#include <math.h>

#define N_OBJ 256
#define C_CLS 151
#define HDIM  512
#define NCROW (N_OBJ * C_CLS)
#define KX    1536
#define CH    (C_CLS * HDIM)

#define LO_SCALE     256.0f
#define LO_INV_SCALE 0.00390625f

/* ------------------- scratch: device globals (no allocs) ------------------ */
__device__ float g_hidden[(size_t)NCROW * HDIM];
__device__ half  g_Xh[(size_t)NCROW * KX];
__device__ float g_Y[(size_t)NCROW * KX];
__device__ float g_YS[(size_t)C_CLS * KX];
__device__ float g_Z1[(size_t)N_OBJ * KX];
__device__ float g_Z2[(size_t)N_OBJ * KX];
__device__ float g_Hbar[N_OBJ * HDIM];
__device__ float g_cM1[C_CLS];
__device__ float g_cM2[C_CLS];
__device__ half  g_RHh[(size_t)NCROW * HDIM];
__device__ half  g_Hh[(size_t)NCROW * HDIM];
__device__ half  g_Hl[(size_t)NCROW * HDIM];
__device__ float g_U5[(size_t)NCROW * HDIM];
__device__ float g_O1[(size_t)NCROW * HDIM];
__device__ float g_S[CH];
__device__ float g_MS1[CH];
__device__ float g_MS2[CH];
__device__ half  g_Wch[(size_t)KX * KX];
__device__ half  g_W5uh[HDIM * HDIM];
__device__ half  g_Woh[HDIM * 2 * HDIM];
__device__ half  g_Wol[HDIM * 2 * HDIM];
__device__ half  g_Ih[N_OBJ * HDIM];
__device__ half  g_Il[N_OBJ * HDIM];
__device__ float g_B2[N_OBJ * HDIM];
__device__ float g_Pcls[(size_t)C_CLS * N_OBJ * C_CLS];

/* ------------------------------ helpers ----------------------------------- */
__device__ __forceinline__ void split_store(float v, half* ph, half* pl)
{
    half hi = __float2half_rn(v);
    *ph = hi;
    *pl = __float2half_rn((v - __half2float(hi)) * LO_SCALE);
}

__device__ __forceinline__ unsigned smem_u32(const void* p)
{
    return (unsigned)__cvta_generic_to_shared(p);
}

__device__ __forceinline__ void ldsm4(unsigned* r, unsigned addr)
{
    asm volatile("ldmatrix.sync.aligned.m8n8.x4.shared.b16 {%0,%1,%2,%3},[%4];"
        : "=r"(r[0]), "=r"(r[1]), "=r"(r[2]), "=r"(r[3]) : "r"(addr));
}

__device__ __forceinline__ void mma16816(float* c, const unsigned* a, const unsigned* b)
{
    asm volatile("mma.sync.aligned.m16n8k16.row.col.f32.f16.f16.f32 "
        "{%0,%1,%2,%3},{%4,%5,%6,%7},{%8,%9},{%0,%1,%2,%3};"
        : "+f"(c[0]), "+f"(c[1]), "+f"(c[2]), "+f"(c[3])
        : "r"(a[0]), "r"(a[1]), "r"(a[2]), "r"(a[3]), "r"(b[0]), "r"(b[1]));
}

__device__ __forceinline__ void cp16(void* dst_smem, const void* src_gmem)
{
    unsigned s = smem_u32(dst_smem);
    asm volatile("cp.async.cg.shared.global [%0], [%1], 16;" :: "r"(s), "l"(src_gmem));
}

__device__ __forceinline__ void cp_commit()
{
    asm volatile("cp.async.commit_group;" ::: "memory");
}

__device__ __forceinline__ void cp_wait0()
{
    asm volatile("cp.async.wait_group 0;" ::: "memory");
}

/* ------------------------- weight concat (hi only) ------------------------ */
__global__ void build_wcat(const float* __restrict__ w3w, const float* __restrict__ w3u,
                           const float* __restrict__ w4w, const float* __restrict__ w4u,
                           const float* __restrict__ w5w)
{
    int idx = blockIdx.x * blockDim.x + threadIdx.x;
    if (idx >= KX * KX) return;
    int o = idx / KX;
    int k = idx - o * KX;
    float v;
    if (o < 512) {
        v = (k < 1024) ? w3w[o * 1024 + k] : w3u[o * 512 + (k - 1024)];
    } else if (o < 1024) {
        int oo = o - 512;
        v = (k < 1024) ? w4w[oo * 1024 + k] : w4u[oo * 512 + (k - 1024)];
    } else {
        int oo = o - 1024;
        v = (k < 1024) ? w5w[oo * 1024 + k] : 0.0f;
    }
    g_Wch[idx] = __float2half_rn(v);
}

__global__ void split_f32(const float* __restrict__ src, half* __restrict__ dh,
                          half* __restrict__ dl, int n)
{
    int idx = blockIdx.x * blockDim.x + threadIdx.x;
    if (idx >= n) return;
    split_store(src[idx], &dh[idx], &dl[idx]);
}

__global__ void conv_f16(const float* __restrict__ src, half* __restrict__ dh, int n)
{
    int idx = blockIdx.x * blockDim.x + threadIdx.x;
    if (idx >= n) return;
    dh[idx] = __float2half_rn(src[idx]);
}

/* ------------------- init hidden[n][c][h] = input[n][h] ------------------- */
__global__ void init_hidden(const float* __restrict__ input)
{
    size_t idx = (size_t)blockIdx.x * blockDim.x + threadIdx.x;
    int h = (int)(idx & (HDIM - 1));
    size_t m = idx >> 9;
    int n = (int)(m / C_CLS);
    g_hidden[idx] = input[(size_t)n * HDIM + h];
}

/* -------------------- S[c][h] = sum_n hidden[n][c][h] --------------------- */
__global__ void colsum_kernel()
{
    int idx = blockIdx.x * blockDim.x + threadIdx.x;
    float s = 0.f;
    #pragma unroll 4
    for (int n = 0; n < N_OBJ; n++) s += g_hidden[(size_t)n * CH + idx];
    g_S[idx] = s;
}

/* ------------- Hbar[n][h] = mean_c hidden[n][c][h] ------------------------ */
__global__ void hbar_kernel()
{
    int idx = blockIdx.x * blockDim.x + threadIdx.x;   /* < N_OBJ*HDIM */
    int n = idx >> 9;
    int h = idx & (HDIM - 1);
    const float* p = g_hidden + (size_t)n * CH + h;
    float s = 0.f;
    for (int c = 0; c < C_CLS; c++) s += p[(size_t)c * HDIM];
    g_Hbar[idx] = s * (1.0f / C_CLS);
}

/* ------------- cM1[d] = sum_c M[c][d] ; cM2[d] = sum_c M[d][c] ------------ */
__global__ void cm_kernel(const float* __restrict__ M)
{
    int d = blockIdx.x * blockDim.x + threadIdx.x;
    if (d >= C_CLS) return;
    float s1 = 0.f, s2 = 0.f;
    for (int c = 0; c < C_CLS; c++) {
        s1 += M[c * C_CLS + d];
        s2 += M[d * C_CLS + c];
    }
    g_cM1[d] = s1;
    g_cM2[d] = s2;
}

/* --------- MS1[d][h]=sum_c M[c][d]S[c][h] ; MS2[d][h]=sum_c M[d][c]S ------ */
__global__ void msprop_kernel(const float* __restrict__ M)
{
    int idx = blockIdx.x * blockDim.x + threadIdx.x;
    int d = idx / HDIM;
    int h = idx - d * HDIM;
    float s1 = 0.f, s2 = 0.f;
    for (int c = 0; c < C_CLS; c++) {
        float sv = g_S[c * HDIM + h];
        s1 += M[c * C_CLS + d] * sv;
        s2 += M[d * C_CLS + c] * sv;
    }
    g_MS1[idx] = s1;
    g_MS2[idx] = s2;
}

/* --- YS[d][o] = sum_{k<1024} MScat[d,k] * Wcat[o,k]  (fp32, exact) --------- */
__global__ __launch_bounds__(256) void ys_kernel(
    const float* __restrict__ w3w, const float* __restrict__ w4w,
    const float* __restrict__ w5w)
{
    __shared__ float ms[1024];
    int d = blockIdx.x;
    int tid = threadIdx.x;
    for (int i = tid; i < 1024; i += 256)
        ms[i] = (i < 512) ? g_MS1[d * HDIM + i] : g_MS2[d * HDIM + (i - 512)];
    __syncthreads();
    for (int o = tid; o < KX; o += 256) {
        const float* w;
        if (o < 512)       w = w3w + (size_t)o * 1024;
        else if (o < 1024) w = w4w + (size_t)(o - 512) * 1024;
        else               w = w5w + (size_t)(o - 1024) * 1024;
        float s = 0.f;
        #pragma unroll 8
        for (int k = 0; k < 1024; k += 4) {
            float4 wv = *(const float4*)(w + k);
            s += wv.x * ms[k] + wv.y * ms[k + 1] + wv.z * ms[k + 2] + wv.w * ms[k + 3];
        }
        g_YS[(size_t)d * KX + o] = s;
    }
}

/* --- Z1[n][o] = sum_{k<512} Hbar[n,k]*W[o,k]; Z2 uses W cols 512..1023 ----- */
__global__ __launch_bounds__(256) void z_kernel(
    const float* __restrict__ w3w, const float* __restrict__ w4w,
    const float* __restrict__ w5w)
{
    __shared__ float hb[512];
    int n = blockIdx.x;
    int tid = threadIdx.x;
    for (int i = tid; i < 512; i += 256)
        hb[i] = g_Hbar[n * HDIM + i];
    __syncthreads();
    for (int o = tid; o < KX; o += 256) {
        const float* w;
        if (o < 512)       w = w3w + (size_t)o * 1024;
        else if (o < 1024) w = w4w + (size_t)(o - 512) * 1024;
        else               w = w5w + (size_t)(o - 1024) * 1024;
        float s1 = 0.f, s2 = 0.f;
        #pragma unroll 8
        for (int k = 0; k < 512; k += 4) {
            float4 w1 = *(const float4*)(w + k);
            float4 w2 = *(const float4*)(w + 512 + k);
            float h0 = hb[k], h1 = hb[k + 1], h2 = hb[k + 2], h3 = hb[k + 3];
            s1 += w1.x * h0 + w1.y * h1 + w1.z * h2 + w1.w * h3;
            s2 += w2.x * h0 + w2.y * h1 + w2.z * h2 + w2.w * h3;
        }
        g_Z1[(size_t)n * KX + o] = s1;
        g_Z2[(size_t)n * KX + o] = s2;
    }
}

/* --- prop + X build: X[(n,d)] = [-a~1 | -a~2 | hidden]  (hi only) ---------- */
/* a~ = sum_c M * (h - hbar)  (common mode removed; handled exactly via Z)    */
#define P_DT 32
#define P_HT 64
__global__ __launch_bounds__(256) void prop_kernel(const float* __restrict__ M)
{
    __shared__ float Hs[8][P_HT];
    __shared__ float M1s[8][P_DT];
    __shared__ float M2s[8][P_DT];
    int n  = blockIdx.z;
    int d0 = blockIdx.y * P_DT;
    int h0 = blockIdx.x * P_HT;
    int tid = threadIdx.x;
    int hx = tid & 31;
    int ty = tid >> 5;
    float a1[4][2] = {{0.f, 0.f}, {0.f, 0.f}, {0.f, 0.f}, {0.f, 0.f}};
    float a2[4][2] = {{0.f, 0.f}, {0.f, 0.f}, {0.f, 0.f}, {0.f, 0.f}};
    const float* Hn = g_hidden + (size_t)n * CH;
    const float* Hb = g_Hbar + (size_t)n * HDIM;

    for (int c0 = 0; c0 < C_CLS; c0 += 8) {
        #pragma unroll
        for (int l = 0; l < 2; l++) {
            int f = tid + l * 256;
            int cc = f >> 6;
            int hh = f & 63;
            int c = c0 + cc;
            Hs[cc][hh] = (c < C_CLS)
                ? (Hn[(size_t)c * HDIM + h0 + hh] - Hb[h0 + hh]) : 0.f;
        }
        {
            int cc = tid >> 5;
            int dd = tid & 31;
            int c = c0 + cc;
            int d = d0 + dd;
            bool ok = (c < C_CLS) && (d < C_CLS);
            M1s[cc][dd] = ok ? M[c * C_CLS + d] : 0.f;
            M2s[cc][dd] = ok ? M[d * C_CLS + c] : 0.f;
        }
        __syncthreads();
        #pragma unroll
        for (int cc = 0; cc < 8; cc++) {
            float hv0 = Hs[cc][hx];
            float hv1 = Hs[cc][hx + 32];
            #pragma unroll
            for (int i = 0; i < 4; i++) {
                float m1 = M1s[cc][ty * 4 + i];
                float m2 = M2s[cc][ty * 4 + i];
                a1[i][0] += m1 * hv0;
                a1[i][1] += m1 * hv1;
                a2[i][0] += m2 * hv0;
                a2[i][1] += m2 * hv1;
            }
        }
        __syncthreads();
    }
    #pragma unroll
    for (int i = 0; i < 4; i++) {
        int d = d0 + ty * 4 + i;
        if (d < C_CLS) {
            size_t r = (size_t)(n * C_CLS + d) * KX;
            #pragma unroll
            for (int q = 0; q < 2; q++) {
                int h = h0 + hx + q * 32;
                g_Xh[r + h]        = __float2half_rn(-a1[i][q]);
                g_Xh[r + 512 + h]  = __float2half_rn(-a2[i][q]);
                g_Xh[r + 1024 + h] = __float2half_rn(Hn[(size_t)d * HDIM + h]);
            }
        }
    }
}

/* ----------- tensor-core GEMM  C[m][n] = sum_k A[m][k] * B[n][k] ----------- */
#define GBM 128
#define GBN 128
#define GBK 32
#define SROW 40
#define SA_IDX(b, hl, r, c) (((((b) * 2 + (hl)) * GBM) + (r)) * SROW + (c))
#define SB_IDX(b, hl, r, c) (((((b) * 2 + (hl)) * GBN) + (r)) * SROW + (c))

__device__ __forceinline__ void gemm_load_stage(
    half* sA, half* sB, int s, int k0, int tid, int m0, int n0,
    const half* Ah, const half* Al, int lda,
    const half* Bh, const half* Bl, int ldb, bool corr)
{
    #pragma unroll
    for (int t = 0; t < 2; t++) {
        int idx = tid + t * 256;
        int row = idx >> 2;
        int ck  = (idx & 3) * 8;
        cp16(&sA[SA_IDX(s, 0, row, ck)], Ah + (size_t)(m0 + row) * lda + k0 + ck);
        cp16(&sB[SB_IDX(s, 0, row, ck)], Bh + (size_t)(n0 + row) * ldb + k0 + ck);
        if (corr) {
            cp16(&sA[SA_IDX(s, 1, row, ck)], Al + (size_t)(m0 + row) * lda + k0 + ck);
            cp16(&sB[SB_IDX(s, 1, row, ck)], Bl + (size_t)(n0 + row) * ldb + k0 + ck);
        }
    }
}

__global__ __launch_bounds__(256, 1) void gemm3(
    const half* __restrict__ Ah, const half* __restrict__ Al, int lda,
    const half* __restrict__ Bh, const half* __restrict__ Bl, int ldb,
    float* __restrict__ Cout, int ldc, int K, int KC)
{
    extern __shared__ half smem[];
    half* sA = smem;
    half* sB = smem + 2 * 2 * GBM * SROW;

    int tid = threadIdx.x;
    int warp = tid >> 5;
    int lane = tid & 31;
    int wm = warp >> 2;
    int wn = warp & 3;
    int m0 = blockIdx.y * GBM;
    int n0 = blockIdx.x * GBN;

    float acc[4][4][4];
    float accS[4][4][4];
    float acl[4][4][4];
    #pragma unroll
    for (int i = 0; i < 4; i++) {
        #pragma unroll
        for (int j = 0; j < 4; j++) {
            #pragma unroll
            for (int q = 0; q < 4; q++) {
                acc[i][j][q]  = 0.f;
                accS[i][j][q] = 0.f;
                acl[i][j][q]  = 0.f;
            }
        }
    }

    gemm_load_stage(sA, sB, 0, 0, tid, m0, n0, Ah, Al, lda, Bh, Bl, ldb, 0 < KC);
    cp_commit();

    int nit = K / GBK;
    for (int it = 0; it < nit; it++) {
        int cur = it & 1;
        bool corr = (it * GBK) < KC;
        cp_wait0();
        __syncthreads();
        if (it + 1 < nit) {
            gemm_load_stage(sA, sB, cur ^ 1, (it + 1) * GBK, tid, m0, n0,
                            Ah, Al, lda, Bh, Bl, ldb, ((it + 1) * GBK) < KC);
            cp_commit();
        }
        #pragma unroll
        for (int ks = 0; ks < 2; ks++) {
            int kk = ks * 16;
            unsigned bhf[2][4];
            unsigned blf[2][4];
            #pragma unroll
            for (int p = 0; p < 2; p++) {
                int nn = wn * 32 + p * 16 + ((lane >> 4) << 3) + (lane & 7);
                int kb = kk + (((lane >> 3) & 1) << 3);
                ldsm4(bhf[p], smem_u32(&sB[SB_IDX(cur, 0, nn, kb)]));
                if (corr)
                    ldsm4(blf[p], smem_u32(&sB[SB_IDX(cur, 1, nn, kb)]));
            }
            #pragma unroll
            for (int mf = 0; mf < 4; mf++) {
                int mm = wm * 64 + mf * 16 + (lane & 15);
                int ka = kk + ((lane >> 4) << 3);
                unsigned ahf[4];
                unsigned alf[4];
                ldsm4(ahf, smem_u32(&sA[SA_IDX(cur, 0, mm, ka)]));
                if (corr)
                    ldsm4(alf, smem_u32(&sA[SA_IDX(cur, 1, mm, ka)]));
                #pragma unroll
                for (int nf = 0; nf < 4; nf++)
                    mma16816(acc[mf][nf], ahf, &bhf[nf >> 1][(nf & 1) * 2]);
                if (corr) {
                    #pragma unroll
                    for (int nf = 0; nf < 4; nf++)
                        mma16816(acl[mf][nf], ahf, &blf[nf >> 1][(nf & 1) * 2]);
                    #pragma unroll
                    for (int nf = 0; nf < 4; nf++)
                        mma16816(acl[mf][nf], alf, &bhf[nf >> 1][(nf & 1) * 2]);
                }
            }
        }
        #pragma unroll
        for (int mf = 0; mf < 4; mf++) {
            #pragma unroll
            for (int nf = 0; nf < 4; nf++) {
                #pragma unroll
                for (int q = 0; q < 4; q++) {
                    accS[mf][nf][q] += acc[mf][nf][q];
                    acc[mf][nf][q] = 0.f;
                }
            }
        }
        __syncthreads();
    }

    int r = lane >> 2;
    int cb = (lane & 3) * 2;
    #pragma unroll
    for (int mf = 0; mf < 4; mf++) {
        #pragma unroll
        for (int nf = 0; nf < 4; nf++) {
            float* Cp = Cout + (size_t)(m0 + wm * 64 + mf * 16 + r) * ldc
                             + (n0 + wn * 32 + nf * 8 + cb);
            Cp[0] = accS[mf][nf][0] + acl[mf][nf][0] * LO_INV_SCALE;
            Cp[1] = accS[mf][nf][1] + acl[mf][nf][1] * LO_INV_SCALE;
            Cp += (size_t)8 * ldc;
            Cp[0] = accS[mf][nf][2] + acl[mf][nf][2] * LO_INV_SCALE;
            Cp[1] = accS[mf][nf][3] + acl[mf][nf][3] * LO_INV_SCALE;
        }
    }
}

/* ------------------------------ pointwise --------------------------------- */
__device__ __forceinline__ float sigmoidf_(float x)
{
    return 1.f / (1.f + expf(-x));
}

__global__ void pw_rv(const float* __restrict__ b4w, const float* __restrict__ b4u)
{
    size_t idx = (size_t)blockIdx.x * blockDim.x + threadIdx.x;
    int h = (int)(idx & (HDIM - 1));
    size_t m = idx >> 9;
    int n = (int)(m / C_CLS);
    int d = (int)(m - (size_t)n * C_CLS);
    size_t o = 512 + h;
    float pre = g_Y[m * KX + o] + g_YS[(size_t)d * KX + o]
              - g_cM1[d] * g_Z1[(size_t)n * KX + o]
              - g_cM2[d] * g_Z2[(size_t)n * KX + o]
              + b4w[h] + b4u[h];
    float rh = sigmoidf_(pre) * g_hidden[idx];
    g_RHh[idx] = __float2half_rn(rh);
}

__global__ void pw_update(const float* __restrict__ b3w, const float* __restrict__ b3u,
                          const float* __restrict__ b5w, const float* __restrict__ b5u)
{
    size_t idx = (size_t)blockIdx.x * blockDim.x + threadIdx.x;
    int h = (int)(idx & (HDIM - 1));
    size_t m = idx >> 9;
    int n = (int)(m / C_CLS);
    int d = (int)(m - (size_t)n * C_CLS);
    const float* ys = g_YS + (size_t)d * KX;
    const float* z1 = g_Z1 + (size_t)n * KX;
    const float* z2 = g_Z2 + (size_t)n * KX;
    float c1 = g_cM1[d];
    float c2 = g_cM2[d];
    float preZ = g_Y[m * KX + h] + ys[h] - c1 * z1[h] - c2 * z2[h]
               + b3w[h] + b3u[h];
    float preH = g_Y[m * KX + 1024 + h] + ys[1024 + h]
               - c1 * z1[1024 + h] - c2 * z2[1024 + h]
               + b5w[h] + g_U5[idx] + b5u[h];
    float z  = sigmoidf_(preZ);
    float hv = tanhf(preH);
    float hp = g_hidden[idx];
    float nh = (1.f - z) * hp + z * hv;
    g_hidden[idx] = nh;
    split_store(nh, &g_Hh[idx], &g_Hl[idx]);
}

__global__ void pw_relu(const float* __restrict__ bout)
{
    size_t idx = (size_t)blockIdx.x * blockDim.x + threadIdx.x;
    int h = (int)(idx & (HDIM - 1));
    size_t m = idx >> 9;
    int n = (int)(m / C_CLS);
    float v = g_O1[idx] + g_B2[n * HDIM + h] + bout[h];
    g_O1[idx] = v > 0.f ? v : 0.f;
}

/* --------------------- classifier: split-K over c ------------------------- */
__global__ __launch_bounds__(160) void cls_partial(const float* __restrict__ wcls)
{
    __shared__ float O1s[32][64];
    int nt = blockIdx.x;
    int ks = blockIdx.y;
    int j = threadIdx.x;
    float acc[32];
    #pragma unroll
    for (int nn = 0; nn < 32; nn++) acc[nn] = 0.f;

    for (int kb = 0; kb < 512; kb += 64) {
        for (int f = threadIdx.x; f < 32 * 64; f += 160) {
            int nn = f >> 6;
            int kk = f & 63;
            O1s[nn][kk] = g_O1[(size_t)(nt * 32 + nn) * CH + ks * 512 + kb + kk];
        }
        __syncthreads();
        if (j < C_CLS) {
            const float* wrow = wcls + (size_t)j * CH + ks * 512 + kb;
            #pragma unroll 4
            for (int kk = 0; kk < 64; kk += 4) {
                float4 w = *(const float4*)(wrow + kk);
                #pragma unroll
                for (int nn = 0; nn < 32; nn++) {
                    float4 o = *(const float4*)&O1s[nn][kk];
                    acc[nn] += w.x * o.x + w.y * o.y + w.z * o.z + w.w * o.w;
                }
            }
        }
        __syncthreads();
    }
    if (j < C_CLS) {
        #pragma unroll
        for (int nn = 0; nn < 32; nn++)
            g_Pcls[((size_t)ks * N_OBJ + nt * 32 + nn) * C_CLS + j] = acc[nn];
    }
}

__global__ void cls_reduce(const float* __restrict__ bcls, float* __restrict__ out)
{
    int idx = blockIdx.x * blockDim.x + threadIdx.x;
    if (idx >= N_OBJ * C_CLS) return;
    int n = idx / C_CLS;
    int j = idx - n * C_CLS;
    float s = bcls[j];
    for (int ks = 0; ks < C_CLS; ks++)
        s += g_Pcls[((size_t)ks * N_OBJ + n) * C_CLS + j];
    out[idx] = s;
}

/* --------------------------------------------------------------------------- */
extern "C" void kernel_launch(void* const* d_in, const int* in_sizes, int n_in,
                              void* d_out, int out_size)
{
    const float* input  = (const float*)d_in[0];
    const float* matrix = (const float*)d_in[1];
    const float* w3w = (const float*)d_in[2];
    const float* b3w = (const float*)d_in[3];
    const float* w3u = (const float*)d_in[4];
    const float* b3u = (const float*)d_in[5];
    const float* w4w = (const float*)d_in[6];
    const float* b4w = (const float*)d_in[7];
    const float* w4u = (const float*)d_in[8];
    const float* b4u = (const float*)d_in[9];
    const float* w5w = (const float*)d_in[10];
    const float* b5w = (const float*)d_in[11];
    const float* w5u = (const float*)d_in[12];
    const float* b5u = (const float*)d_in[13];
    const float* wout = (const float*)d_in[14];
    const float* bout = (const float*)d_in[15];
    const float* wcls = (const float*)d_in[16];
    const float* bcls = (const float*)d_in[17];
    float* out = (float*)d_out;

    void* tmp = 0;
    float* pY;
    float* pU5;
    float* pO1;
    float* pB2;
    half* pXh;
    half* pWch;
    half* pRHh;
    half* pHh;
    half* pHl;
    half* pW5uh;
    half* pWoh;
    half* pWol;
    half* pIh;
    half* pIl;

    cudaGetSymbolAddress(&tmp, g_Y);     pY    = (float*)tmp;
    cudaGetSymbolAddress(&tmp, g_U5);    pU5   = (float*)tmp;
    cudaGetSymbolAddress(&tmp, g_O1);    pO1   = (float*)tmp;
    cudaGetSymbolAddress(&tmp, g_B2);    pB2   = (float*)tmp;
    cudaGetSymbolAddress(&tmp, g_Xh);    pXh   = (half*)tmp;
    cudaGetSymbolAddress(&tmp, g_Wch);   pWch  = (half*)tmp;
    cudaGetSymbolAddress(&tmp, g_RHh);   pRHh  = (half*)tmp;
    cudaGetSymbolAddress(&tmp, g_Hh);    pHh   = (half*)tmp;
    cudaGetSymbolAddress(&tmp, g_Hl);    pHl   = (half*)tmp;
    cudaGetSymbolAddress(&tmp, g_W5uh);  pW5uh = (half*)tmp;
    cudaGetSymbolAddress(&tmp, g_Woh);   pWoh  = (half*)tmp;
    cudaGetSymbolAddress(&tmp, g_Wol);   pWol  = (half*)tmp;
    cudaGetSymbolAddress(&tmp, g_Ih);    pIh   = (half*)tmp;
    cudaGetSymbolAddress(&tmp, g_Il);    pIl   = (half*)tmp;

    const int GEMM_SMEM = 2 * 2 * (GBM + GBN) * SROW * (int)sizeof(half);
    cudaFuncSetAttribute(gemm3, cudaFuncAttributeMaxDynamicSharedMemorySize, GEMM_SMEM);

    const int PW_BLOCKS = (int)(((size_t)NCROW * HDIM) / 256);
    const int CH_BLOCKS = CH / 256;
    const int NH_BLOCKS = (N_OBJ * HDIM) / 256;

    build_wcat<<<(KX * KX + 255) / 256, 256>>>(w3w, w3u, w4w, w4u, w5w);
    split_f32<<<(HDIM * 2 * HDIM + 255) / 256, 256>>>(wout, pWoh, pWol,
                                                      HDIM * 2 * HDIM);
    split_f32<<<(N_OBJ * HDIM + 255) / 256, 256>>>(input, pIh, pIl,
                                                   N_OBJ * HDIM);
    /* B2 = input @ Wo2^T — full corrections (launch #3, profiled) */
    gemm3<<<dim3(HDIM / GBN, N_OBJ / GBM), 256, GEMM_SMEM>>>(
        pIh, pIl, HDIM, pWoh + 512, pWol + 512, 2 * HDIM, pB2, HDIM, HDIM, HDIM);
    conv_f16<<<(HDIM * HDIM + 255) / 256, 256>>>(w5u, pW5uh, HDIM * HDIM);
    cm_kernel<<<1, 256>>>(matrix);
    init_hidden<<<PW_BLOCKS, 256>>>(input);

    for (int t = 0; t < 3; t++) {
        colsum_kernel<<<CH_BLOCKS, 256>>>();
        msprop_kernel<<<CH_BLOCKS, 256>>>(matrix);
        hbar_kernel<<<NH_BLOCKS, 256>>>();
        ys_kernel<<<C_CLS, 256>>>(w3w, w4w, w5w);
        z_kernel<<<N_OBJ, 256>>>(w3w, w4w, w5w);
        prop_kernel<<<dim3(HDIM / P_HT, (C_CLS + P_DT - 1) / P_DT, N_OBJ), 256>>>(matrix);
        /* Yres = [-a~1 | -a~2 | h] @ Wcat^T : hi-only (KC=0) */
        gemm3<<<dim3(KX / GBN, NCROW / GBM), 256, GEMM_SMEM>>>(
            pXh, pXh, KX, pWch, pWch, KX, pY, KX, KX, 0);
        pw_rv<<<PW_BLOCKS, 256>>>(b4w, b4u);
        /* U5 = (rv*h) @ W5u^T : hi-only */
        gemm3<<<dim3(HDIM / GBN, NCROW / GBM), 256, GEMM_SMEM>>>(
            pRHh, pRHh, HDIM, pW5uh, pW5uh, HDIM, pU5, HDIM, HDIM, 0);
        pw_update<<<PW_BLOCKS, 256>>>(b3w, b3u, b5w, b5u);
    }

    /* O1 = hidden @ Wo1^T — full corrections (classifier-facing) */
    gemm3<<<dim3(HDIM / GBN, NCROW / GBM), 256, GEMM_SMEM>>>(
        pHh, pHl, HDIM, pWoh, pWol, 2 * HDIM, pO1, HDIM, HDIM, HDIM);
    pw_relu<<<PW_BLOCKS, 256>>>(bout);

    cls_partial<<<dim3(N_OBJ / 32, C_CLS), 160>>>(wcls);
    cls_reduce<<<(N_OBJ * C_CLS + 255) / 256, 256>>>(bcls, out);
}

// round 14
// speedup vs baseline: 1.2460x; 1.2460x over previous
#include <cuda_runtime.h>
#include <cuda_fp16.h>
#include <math.h>

#define N_OBJ 256
#define C_CLS 151
#define HDIM  512
#define NCROW (N_OBJ * C_CLS)
#define KX    1536
#define CH    (C_CLS * HDIM)
#define DPAD  256               /* C_CLS padded to MMA tile */

#define LO_SCALE     256.0f
#define LO_INV_SCALE 0.00390625f

/* ------------------- scratch: device globals (no allocs) ------------------ */
__device__ float g_hidden[(size_t)NCROW * HDIM];
__device__ half  g_Xh[(size_t)NCROW * KX];
__device__ float g_Y[(size_t)NCROW * KX];
__device__ float g_YS[(size_t)DPAD * KX];
__device__ float g_Z1[(size_t)N_OBJ * KX];
__device__ float g_Z2[(size_t)N_OBJ * KX];
__device__ float g_Hbar[N_OBJ * HDIM];
__device__ half  g_Hbh[N_OBJ * HDIM];
__device__ half  g_Hbl[N_OBJ * HDIM];
__device__ half  g_MSh[(size_t)DPAD * 1024];
__device__ half  g_MSl[(size_t)DPAD * 1024];
__device__ float g_cM1[C_CLS];
__device__ float g_cM2[C_CLS];
__device__ half  g_RHh[(size_t)NCROW * HDIM];
__device__ half  g_Hh[(size_t)NCROW * HDIM];
__device__ half  g_Hl[(size_t)NCROW * HDIM];
__device__ float g_U5[(size_t)NCROW * HDIM];
__device__ float g_O1[(size_t)NCROW * HDIM];
__device__ float g_S[CH];
__device__ float g_MS1[CH];
__device__ float g_MS2[CH];
__device__ half  g_Wch[(size_t)KX * KX];
__device__ half  g_Wcl[(size_t)KX * KX];
__device__ half  g_W5uh[HDIM * HDIM];
__device__ half  g_Woh[HDIM * 2 * HDIM];
__device__ half  g_Wol[HDIM * 2 * HDIM];
__device__ half  g_Ih[N_OBJ * HDIM];
__device__ half  g_Il[N_OBJ * HDIM];
__device__ float g_B2[N_OBJ * HDIM];
__device__ float g_Pcls[(size_t)C_CLS * N_OBJ * C_CLS];

/* ------------------------------ helpers ----------------------------------- */
__device__ __forceinline__ void split_store(float v, half* ph, half* pl)
{
    half hi = __float2half_rn(v);
    *ph = hi;
    *pl = __float2half_rn((v - __half2float(hi)) * LO_SCALE);
}

__device__ __forceinline__ unsigned smem_u32(const void* p)
{
    return (unsigned)__cvta_generic_to_shared(p);
}

__device__ __forceinline__ void ldsm4(unsigned* r, unsigned addr)
{
    asm volatile("ldmatrix.sync.aligned.m8n8.x4.shared.b16 {%0,%1,%2,%3},[%4];"
        : "=r"(r[0]), "=r"(r[1]), "=r"(r[2]), "=r"(r[3]) : "r"(addr));
}

__device__ __forceinline__ void mma16816(float* c, const unsigned* a, const unsigned* b)
{
    asm volatile("mma.sync.aligned.m16n8k16.row.col.f32.f16.f16.f32 "
        "{%0,%1,%2,%3},{%4,%5,%6,%7},{%8,%9},{%0,%1,%2,%3};"
        : "+f"(c[0]), "+f"(c[1]), "+f"(c[2]), "+f"(c[3])
        : "r"(a[0]), "r"(a[1]), "r"(a[2]), "r"(a[3]), "r"(b[0]), "r"(b[1]));
}

__device__ __forceinline__ void cp16(void* dst_smem, const void* src_gmem)
{
    unsigned s = smem_u32(dst_smem);
    asm volatile("cp.async.cg.shared.global [%0], [%1], 16;" :: "r"(s), "l"(src_gmem));
}

__device__ __forceinline__ void cp_commit()
{
    asm volatile("cp.async.commit_group;" ::: "memory");
}

__device__ __forceinline__ void cp_wait0()
{
    asm volatile("cp.async.wait_group 0;" ::: "memory");
}

/* ------------------------- weight concat + split --------------------------- */
__global__ void build_wcat(const float* __restrict__ w3w, const float* __restrict__ w3u,
                           const float* __restrict__ w4w, const float* __restrict__ w4u,
                           const float* __restrict__ w5w)
{
    int idx = blockIdx.x * blockDim.x + threadIdx.x;
    if (idx >= KX * KX) return;
    int o = idx / KX;
    int k = idx - o * KX;
    float v;
    if (o < 512) {
        v = (k < 1024) ? w3w[o * 1024 + k] : w3u[o * 512 + (k - 1024)];
    } else if (o < 1024) {
        int oo = o - 512;
        v = (k < 1024) ? w4w[oo * 1024 + k] : w4u[oo * 512 + (k - 1024)];
    } else {
        int oo = o - 1024;
        v = (k < 1024) ? w5w[oo * 1024 + k] : 0.0f;
    }
    split_store(v, &g_Wch[idx], &g_Wcl[idx]);
}

__global__ void split_f32(const float* __restrict__ src, half* __restrict__ dh,
                          half* __restrict__ dl, int n)
{
    int idx = blockIdx.x * blockDim.x + threadIdx.x;
    if (idx >= n) return;
    split_store(src[idx], &dh[idx], &dl[idx]);
}

__global__ void conv_f16(const float* __restrict__ src, half* __restrict__ dh, int n)
{
    int idx = blockIdx.x * blockDim.x + threadIdx.x;
    if (idx >= n) return;
    dh[idx] = __float2half_rn(src[idx]);
}

/* ------------------- init hidden[n][c][h] = input[n][h] ------------------- */
__global__ void init_hidden(const float* __restrict__ input)
{
    size_t idx = (size_t)blockIdx.x * blockDim.x + threadIdx.x;
    int h = (int)(idx & (HDIM - 1));
    size_t m = idx >> 9;
    int n = (int)(m / C_CLS);
    g_hidden[idx] = input[(size_t)n * HDIM + h];
}

/* -------------------- S[c][h] = sum_n hidden[n][c][h] --------------------- */
__global__ void colsum_kernel()
{
    int idx = blockIdx.x * blockDim.x + threadIdx.x;
    float s = 0.f;
    #pragma unroll 4
    for (int n = 0; n < N_OBJ; n++) s += g_hidden[(size_t)n * CH + idx];
    g_S[idx] = s;
}

/* ------------- Hbar[n][h] = mean_c hidden[n][c][h]  (+ hi/lo split) ------- */
__global__ void hbar_kernel()
{
    int idx = blockIdx.x * blockDim.x + threadIdx.x;   /* < N_OBJ*HDIM */
    int n = idx >> 9;
    int h = idx & (HDIM - 1);
    const float* p = g_hidden + (size_t)n * CH + h;
    float s = 0.f;
    for (int c = 0; c < C_CLS; c++) s += p[(size_t)c * HDIM];
    float hb = s * (1.0f / C_CLS);
    g_Hbar[idx] = hb;
    split_store(hb, &g_Hbh[idx], &g_Hbl[idx]);
}

/* ------------- cM1[d] = sum_c M[c][d] ; cM2[d] = sum_c M[d][c] ------------ */
__global__ void cm_kernel(const float* __restrict__ M)
{
    int d = blockIdx.x * blockDim.x + threadIdx.x;
    if (d >= C_CLS) return;
    float s1 = 0.f, s2 = 0.f;
    for (int c = 0; c < C_CLS; c++) {
        s1 += M[c * C_CLS + d];
        s2 += M[d * C_CLS + c];
    }
    g_cM1[d] = s1;
    g_cM2[d] = s2;
}

/* --------- MS1[d][h]=sum_c M[c][d]S[c][h] ; MS2[d][h]=sum_c M[d][c]S ------ */
__global__ void msprop_kernel(const float* __restrict__ M)
{
    int idx = blockIdx.x * blockDim.x + threadIdx.x;
    int d = idx / HDIM;
    int h = idx - d * HDIM;
    float s1 = 0.f, s2 = 0.f;
    for (int c = 0; c < C_CLS; c++) {
        float sv = g_S[c * HDIM + h];
        s1 += M[c * C_CLS + d] * sv;
        s2 += M[d * C_CLS + c] * sv;
    }
    g_MS1[idx] = s1;
    g_MS2[idx] = s2;
}

/* --- MScat padded split: MSh/MSl[d][k], d<DPAD, k<1024 --------------------- */
__global__ void ms_split_kernel()
{
    int idx = blockIdx.x * blockDim.x + threadIdx.x;   /* < DPAD*1024 */
    int d = idx >> 10;
    int k = idx & 1023;
    float v = 0.f;
    if (d < C_CLS)
        v = (k < 512) ? g_MS1[d * HDIM + k] : g_MS2[d * HDIM + (k - 512)];
    split_store(v, &g_MSh[idx], &g_MSl[idx]);
}

/* --- prop + X build: X[(n,d)] = [-a~1 | -a~2 | hidden]  (hi only) ---------- */
#define P_DT 32
#define P_HT 64
__global__ __launch_bounds__(256) void prop_kernel(const float* __restrict__ M)
{
    __shared__ float Hs[8][P_HT];
    __shared__ float M1s[8][P_DT];
    __shared__ float M2s[8][P_DT];
    int n  = blockIdx.z;
    int d0 = blockIdx.y * P_DT;
    int h0 = blockIdx.x * P_HT;
    int tid = threadIdx.x;
    int hx = tid & 31;
    int ty = tid >> 5;
    float a1[4][2] = {{0.f, 0.f}, {0.f, 0.f}, {0.f, 0.f}, {0.f, 0.f}};
    float a2[4][2] = {{0.f, 0.f}, {0.f, 0.f}, {0.f, 0.f}, {0.f, 0.f}};
    const float* Hn = g_hidden + (size_t)n * CH;
    const float* Hb = g_Hbar + (size_t)n * HDIM;

    for (int c0 = 0; c0 < C_CLS; c0 += 8) {
        #pragma unroll
        for (int l = 0; l < 2; l++) {
            int f = tid + l * 256;
            int cc = f >> 6;
            int hh = f & 63;
            int c = c0 + cc;
            Hs[cc][hh] = (c < C_CLS)
                ? (Hn[(size_t)c * HDIM + h0 + hh] - Hb[h0 + hh]) : 0.f;
        }
        {
            int cc = tid >> 5;
            int dd = tid & 31;
            int c = c0 + cc;
            int d = d0 + dd;
            bool ok = (c < C_CLS) && (d < C_CLS);
            M1s[cc][dd] = ok ? M[c * C_CLS + d] : 0.f;
            M2s[cc][dd] = ok ? M[d * C_CLS + c] : 0.f;
        }
        __syncthreads();
        #pragma unroll
        for (int cc = 0; cc < 8; cc++) {
            float hv0 = Hs[cc][hx];
            float hv1 = Hs[cc][hx + 32];
            #pragma unroll
            for (int i = 0; i < 4; i++) {
                float m1 = M1s[cc][ty * 4 + i];
                float m2 = M2s[cc][ty * 4 + i];
                a1[i][0] += m1 * hv0;
                a1[i][1] += m1 * hv1;
                a2[i][0] += m2 * hv0;
                a2[i][1] += m2 * hv1;
            }
        }
        __syncthreads();
    }
    #pragma unroll
    for (int i = 0; i < 4; i++) {
        int d = d0 + ty * 4 + i;
        if (d < C_CLS) {
            size_t r = (size_t)(n * C_CLS + d) * KX;
            #pragma unroll
            for (int q = 0; q < 2; q++) {
                int h = h0 + hx + q * 32;
                g_Xh[r + h]        = __float2half_rn(-a1[i][q]);
                g_Xh[r + 512 + h]  = __float2half_rn(-a2[i][q]);
                g_Xh[r + 1024 + h] = __float2half_rn(Hn[(size_t)d * HDIM + h]);
            }
        }
    }
}

/* ----------- tensor-core GEMM  C[m][n] = sum_k A[m][k] * B[n][k] ----------- */
#define GBM 128
#define GBN 128
#define GBK 32
#define SROW 40
#define SA_IDX(b, hl, r, c) (((((b) * 2 + (hl)) * GBM) + (r)) * SROW + (c))
#define SB_IDX(b, hl, r, c) (((((b) * 2 + (hl)) * GBN) + (r)) * SROW + (c))

__device__ __forceinline__ void gemm_load_stage(
    half* sA, half* sB, int s, int k0, int tid, int m0, int n0,
    const half* Ah, const half* Al, int lda,
    const half* Bh, const half* Bl, int ldb, bool corr)
{
    #pragma unroll
    for (int t = 0; t < 2; t++) {
        int idx = tid + t * 256;
        int row = idx >> 2;
        int ck  = (idx & 3) * 8;
        cp16(&sA[SA_IDX(s, 0, row, ck)], Ah + (size_t)(m0 + row) * lda + k0 + ck);
        cp16(&sB[SB_IDX(s, 0, row, ck)], Bh + (size_t)(n0 + row) * ldb + k0 + ck);
        if (corr) {
            cp16(&sA[SA_IDX(s, 1, row, ck)], Al + (size_t)(m0 + row) * lda + k0 + ck);
            cp16(&sB[SB_IDX(s, 1, row, ck)], Bl + (size_t)(n0 + row) * ldb + k0 + ck);
        }
    }
}

__global__ __launch_bounds__(256, 1) void gemm3(
    const half* __restrict__ Ah, const half* __restrict__ Al, int lda,
    const half* __restrict__ Bh, const half* __restrict__ Bl, int ldb,
    float* __restrict__ Cout, int ldc, int K, int KC)
{
    extern __shared__ half smem[];
    half* sA = smem;
    half* sB = smem + 2 * 2 * GBM * SROW;

    int tid = threadIdx.x;
    int warp = tid >> 5;
    int lane = tid & 31;
    int wm = warp >> 2;
    int wn = warp & 3;
    int m0 = blockIdx.y * GBM;
    int n0 = blockIdx.x * GBN;

    float acc[4][4][4];
    float accS[4][4][4];
    float acl[4][4][4];
    #pragma unroll
    for (int i = 0; i < 4; i++) {
        #pragma unroll
        for (int j = 0; j < 4; j++) {
            #pragma unroll
            for (int q = 0; q < 4; q++) {
                acc[i][j][q]  = 0.f;
                accS[i][j][q] = 0.f;
                acl[i][j][q]  = 0.f;
            }
        }
    }

    gemm_load_stage(sA, sB, 0, 0, tid, m0, n0, Ah, Al, lda, Bh, Bl, ldb, 0 < KC);
    cp_commit();

    int nit = K / GBK;
    for (int it = 0; it < nit; it++) {
        int cur = it & 1;
        bool corr = (it * GBK) < KC;
        cp_wait0();
        __syncthreads();
        if (it + 1 < nit) {
            gemm_load_stage(sA, sB, cur ^ 1, (it + 1) * GBK, tid, m0, n0,
                            Ah, Al, lda, Bh, Bl, ldb, ((it + 1) * GBK) < KC);
            cp_commit();
        }
        #pragma unroll
        for (int ks = 0; ks < 2; ks++) {
            int kk = ks * 16;
            unsigned bhf[2][4];
            unsigned blf[2][4];
            #pragma unroll
            for (int p = 0; p < 2; p++) {
                int nn = wn * 32 + p * 16 + ((lane >> 4) << 3) + (lane & 7);
                int kb = kk + (((lane >> 3) & 1) << 3);
                ldsm4(bhf[p], smem_u32(&sB[SB_IDX(cur, 0, nn, kb)]));
                if (corr)
                    ldsm4(blf[p], smem_u32(&sB[SB_IDX(cur, 1, nn, kb)]));
            }
            #pragma unroll
            for (int mf = 0; mf < 4; mf++) {
                int mm = wm * 64 + mf * 16 + (lane & 15);
                int ka = kk + ((lane >> 4) << 3);
                unsigned ahf[4];
                unsigned alf[4];
                ldsm4(ahf, smem_u32(&sA[SA_IDX(cur, 0, mm, ka)]));
                if (corr)
                    ldsm4(alf, smem_u32(&sA[SA_IDX(cur, 1, mm, ka)]));
                #pragma unroll
                for (int nf = 0; nf < 4; nf++)
                    mma16816(acc[mf][nf], ahf, &bhf[nf >> 1][(nf & 1) * 2]);
                if (corr) {
                    #pragma unroll
                    for (int nf = 0; nf < 4; nf++)
                        mma16816(acl[mf][nf], ahf, &blf[nf >> 1][(nf & 1) * 2]);
                    #pragma unroll
                    for (int nf = 0; nf < 4; nf++)
                        mma16816(acl[mf][nf], alf, &bhf[nf >> 1][(nf & 1) * 2]);
                }
            }
        }
        #pragma unroll
        for (int mf = 0; mf < 4; mf++) {
            #pragma unroll
            for (int nf = 0; nf < 4; nf++) {
                #pragma unroll
                for (int q = 0; q < 4; q++) {
                    accS[mf][nf][q] += acc[mf][nf][q];
                    acc[mf][nf][q] = 0.f;
                }
            }
        }
        __syncthreads();
    }

    int r = lane >> 2;
    int cb = (lane & 3) * 2;
    #pragma unroll
    for (int mf = 0; mf < 4; mf++) {
        #pragma unroll
        for (int nf = 0; nf < 4; nf++) {
            float* Cp = Cout + (size_t)(m0 + wm * 64 + mf * 16 + r) * ldc
                             + (n0 + wn * 32 + nf * 8 + cb);
            Cp[0] = accS[mf][nf][0] + acl[mf][nf][0] * LO_INV_SCALE;
            Cp[1] = accS[mf][nf][1] + acl[mf][nf][1] * LO_INV_SCALE;
            Cp += (size_t)8 * ldc;
            Cp[0] = accS[mf][nf][2] + acl[mf][nf][2] * LO_INV_SCALE;
            Cp[1] = accS[mf][nf][3] + acl[mf][nf][3] * LO_INV_SCALE;
        }
    }
}

/* ------------------------------ pointwise --------------------------------- */
__device__ __forceinline__ float sigmoidf_(float x)
{
    return 1.f / (1.f + expf(-x));
}

__global__ void pw_rv(const float* __restrict__ b4w, const float* __restrict__ b4u)
{
    size_t idx = (size_t)blockIdx.x * blockDim.x + threadIdx.x;
    int h = (int)(idx & (HDIM - 1));
    size_t m = idx >> 9;
    int n = (int)(m / C_CLS);
    int d = (int)(m - (size_t)n * C_CLS);
    size_t o = 512 + h;
    float pre = g_Y[m * KX + o] + g_YS[(size_t)d * KX + o]
              - g_cM1[d] * g_Z1[(size_t)n * KX + o]
              - g_cM2[d] * g_Z2[(size_t)n * KX + o]
              + b4w[h] + b4u[h];
    float rh = sigmoidf_(pre) * g_hidden[idx];
    g_RHh[idx] = __float2half_rn(rh);
}

__global__ void pw_update(const float* __restrict__ b3w, const float* __restrict__ b3u,
                          const float* __restrict__ b5w, const float* __restrict__ b5u)
{
    size_t idx = (size_t)blockIdx.x * blockDim.x + threadIdx.x;
    int h = (int)(idx & (HDIM - 1));
    size_t m = idx >> 9;
    int n = (int)(m / C_CLS);
    int d = (int)(m - (size_t)n * C_CLS);
    const float* ys = g_YS + (size_t)d * KX;
    const float* z1 = g_Z1 + (size_t)n * KX;
    const float* z2 = g_Z2 + (size_t)n * KX;
    float c1 = g_cM1[d];
    float c2 = g_cM2[d];
    float preZ = g_Y[m * KX + h] + ys[h] - c1 * z1[h] - c2 * z2[h]
               + b3w[h] + b3u[h];
    float preH = g_Y[m * KX + 1024 + h] + ys[1024 + h]
               - c1 * z1[1024 + h] - c2 * z2[1024 + h]
               + b5w[h] + g_U5[idx] + b5u[h];
    float z  = sigmoidf_(preZ);
    float hv = tanhf(preH);
    float hp = g_hidden[idx];
    float nh = (1.f - z) * hp + z * hv;
    g_hidden[idx] = nh;
    split_store(nh, &g_Hh[idx], &g_Hl[idx]);
}

__global__ void pw_relu(const float* __restrict__ bout)
{
    size_t idx = (size_t)blockIdx.x * blockDim.x + threadIdx.x;
    int h = (int)(idx & (HDIM - 1));
    size_t m = idx >> 9;
    int n = (int)(m / C_CLS);
    float v = g_O1[idx] + g_B2[n * HDIM + h] + bout[h];
    g_O1[idx] = v > 0.f ? v : 0.f;
}

/* --------------------- classifier: split-K over c ------------------------- */
__global__ __launch_bounds__(160) void cls_partial(const float* __restrict__ wcls)
{
    __shared__ float O1s[32][64];
    int nt = blockIdx.x;
    int ks = blockIdx.y;
    int j = threadIdx.x;
    float acc[32];
    #pragma unroll
    for (int nn = 0; nn < 32; nn++) acc[nn] = 0.f;

    for (int kb = 0; kb < 512; kb += 64) {
        for (int f = threadIdx.x; f < 32 * 64; f += 160) {
            int nn = f >> 6;
            int kk = f & 63;
            O1s[nn][kk] = g_O1[(size_t)(nt * 32 + nn) * CH + ks * 512 + kb + kk];
        }
        __syncthreads();
        if (j < C_CLS) {
            const float* wrow = wcls + (size_t)j * CH + ks * 512 + kb;
            #pragma unroll 4
            for (int kk = 0; kk < 64; kk += 4) {
                float4 w = *(const float4*)(wrow + kk);
                #pragma unroll
                for (int nn = 0; nn < 32; nn++) {
                    float4 o = *(const float4*)&O1s[nn][kk];
                    acc[nn] += w.x * o.x + w.y * o.y + w.z * o.z + w.w * o.w;
                }
            }
        }
        __syncthreads();
    }
    if (j < C_CLS) {
        #pragma unroll
        for (int nn = 0; nn < 32; nn++)
            g_Pcls[((size_t)ks * N_OBJ + nt * 32 + nn) * C_CLS + j] = acc[nn];
    }
}

__global__ void cls_reduce(const float* __restrict__ bcls, float* __restrict__ out)
{
    int idx = blockIdx.x * blockDim.x + threadIdx.x;
    if (idx >= N_OBJ * C_CLS) return;
    int n = idx / C_CLS;
    int j = idx - n * C_CLS;
    float s = bcls[j];
    for (int ks = 0; ks < C_CLS; ks++)
        s += g_Pcls[((size_t)ks * N_OBJ + n) * C_CLS + j];
    out[idx] = s;
}

/* --------------------------------------------------------------------------- */
extern "C" void kernel_launch(void* const* d_in, const int* in_sizes, int n_in,
                              void* d_out, int out_size)
{
    const float* input  = (const float*)d_in[0];
    const float* matrix = (const float*)d_in[1];
    const float* w3w = (const float*)d_in[2];
    const float* b3w = (const float*)d_in[3];
    const float* w3u = (const float*)d_in[4];
    const float* b3u = (const float*)d_in[5];
    const float* w4w = (const float*)d_in[6];
    const float* b4w = (const float*)d_in[7];
    const float* w4u = (const float*)d_in[8];
    const float* b4u = (const float*)d_in[9];
    const float* w5w = (const float*)d_in[10];
    const float* b5w = (const float*)d_in[11];
    const float* w5u = (const float*)d_in[12];
    const float* b5u = (const float*)d_in[13];
    const float* wout = (const float*)d_in[14];
    const float* bout = (const float*)d_in[15];
    const float* wcls = (const float*)d_in[16];
    const float* bcls = (const float*)d_in[17];
    float* out = (float*)d_out;

    void* tmp = 0;
    float* pY;
    float* pYS;
    float* pZ1;
    float* pZ2;
    float* pU5;
    float* pO1;
    float* pB2;
    half* pXh;
    half* pWch;
    half* pWcl;
    half* pRHh;
    half* pHh;
    half* pHl;
    half* pW5uh;
    half* pWoh;
    half* pWol;
    half* pIh;
    half* pIl;
    half* pMSh;
    half* pMSl;
    half* pHbh;
    half* pHbl;

    cudaGetSymbolAddress(&tmp, g_Y);     pY    = (float*)tmp;
    cudaGetSymbolAddress(&tmp, g_YS);    pYS   = (float*)tmp;
    cudaGetSymbolAddress(&tmp, g_Z1);    pZ1   = (float*)tmp;
    cudaGetSymbolAddress(&tmp, g_Z2);    pZ2   = (float*)tmp;
    cudaGetSymbolAddress(&tmp, g_U5);    pU5   = (float*)tmp;
    cudaGetSymbolAddress(&tmp, g_O1);    pO1   = (float*)tmp;
    cudaGetSymbolAddress(&tmp, g_B2);    pB2   = (float*)tmp;
    cudaGetSymbolAddress(&tmp, g_Xh);    pXh   = (half*)tmp;
    cudaGetSymbolAddress(&tmp, g_Wch);   pWch  = (half*)tmp;
    cudaGetSymbolAddress(&tmp, g_Wcl);   pWcl  = (half*)tmp;
    cudaGetSymbolAddress(&tmp, g_RHh);   pRHh  = (half*)tmp;
    cudaGetSymbolAddress(&tmp, g_Hh);    pHh   = (half*)tmp;
    cudaGetSymbolAddress(&tmp, g_Hl);    pHl   = (half*)tmp;
    cudaGetSymbolAddress(&tmp, g_W5uh);  pW5uh = (half*)tmp;
    cudaGetSymbolAddress(&tmp, g_Woh);   pWoh  = (half*)tmp;
    cudaGetSymbolAddress(&tmp, g_Wol);   pWol  = (half*)tmp;
    cudaGetSymbolAddress(&tmp, g_Ih);    pIh   = (half*)tmp;
    cudaGetSymbolAddress(&tmp, g_Il);    pIl   = (half*)tmp;
    cudaGetSymbolAddress(&tmp, g_MSh);   pMSh  = (half*)tmp;
    cudaGetSymbolAddress(&tmp, g_MSl);   pMSl  = (half*)tmp;
    cudaGetSymbolAddress(&tmp, g_Hbh);   pHbh  = (half*)tmp;
    cudaGetSymbolAddress(&tmp, g_Hbl);   pHbl  = (half*)tmp;

    const int GEMM_SMEM = 2 * 2 * (GBM + GBN) * SROW * (int)sizeof(half);
    cudaFuncSetAttribute(gemm3, cudaFuncAttributeMaxDynamicSharedMemorySize, GEMM_SMEM);

    const int PW_BLOCKS = (int)(((size_t)NCROW * HDIM) / 256);
    const int CH_BLOCKS = CH / 256;
    const int NH_BLOCKS = (N_OBJ * HDIM) / 256;

    build_wcat<<<(KX * KX + 255) / 256, 256>>>(w3w, w3u, w4w, w4u, w5w);
    split_f32<<<(HDIM * 2 * HDIM + 255) / 256, 256>>>(wout, pWoh, pWol,
                                                      HDIM * 2 * HDIM);
    split_f32<<<(N_OBJ * HDIM + 255) / 256, 256>>>(input, pIh, pIl,
                                                   N_OBJ * HDIM);
    /* B2 = input @ Wo2^T — full corrections (launch #3, profiled) */
    gemm3<<<dim3(HDIM / GBN, N_OBJ / GBM), 256, GEMM_SMEM>>>(
        pIh, pIl, HDIM, pWoh + 512, pWol + 512, 2 * HDIM, pB2, HDIM, HDIM, HDIM);
    conv_f16<<<(HDIM * HDIM + 255) / 256, 256>>>(w5u, pW5uh, HDIM * HDIM);
    cm_kernel<<<1, 256>>>(matrix);
    init_hidden<<<PW_BLOCKS, 256>>>(input);

    for (int t = 0; t < 3; t++) {
        colsum_kernel<<<CH_BLOCKS, 256>>>();
        msprop_kernel<<<CH_BLOCKS, 256>>>(matrix);
        hbar_kernel<<<NH_BLOCKS, 256>>>();
        ms_split_kernel<<<(DPAD * 1024) / 256, 256>>>();
        /* YS = MScat @ Wcat[:, :1024]^T — fp16x3 full corrections */
        gemm3<<<dim3(KX / GBN, DPAD / GBM), 256, GEMM_SMEM>>>(
            pMSh, pMSl, 1024, pWch, pWcl, KX, pYS, KX, 1024, 1024);
        /* Z1 = Hbar @ Wcat[:, 0:512]^T ; Z2 = Hbar @ Wcat[:, 512:1024]^T */
        gemm3<<<dim3(KX / GBN, N_OBJ / GBM), 256, GEMM_SMEM>>>(
            pHbh, pHbl, HDIM, pWch, pWcl, KX, pZ1, KX, HDIM, HDIM);
        gemm3<<<dim3(KX / GBN, N_OBJ / GBM), 256, GEMM_SMEM>>>(
            pHbh, pHbl, HDIM, pWch + 512, pWcl + 512, KX, pZ2, KX, HDIM, HDIM);
        prop_kernel<<<dim3(HDIM / P_HT, (C_CLS + P_DT - 1) / P_DT, N_OBJ), 256>>>(matrix);
        /* Yres = [-a~1 | -a~2 | h] @ Wcat^T : hi-only (KC=0) */
        gemm3<<<dim3(KX / GBN, NCROW / GBM), 256, GEMM_SMEM>>>(
            pXh, pXh, KX, pWch, pWch, KX, pY, KX, KX, 0);
        pw_rv<<<PW_BLOCKS, 256>>>(b4w, b4u);
        /* U5 = (rv*h) @ W5u^T : hi-only */
        gemm3<<<dim3(HDIM / GBN, NCROW / GBM), 256, GEMM_SMEM>>>(
            pRHh, pRHh, HDIM, pW5uh, pW5uh, HDIM, pU5, HDIM, HDIM, 0);
        pw_update<<<PW_BLOCKS, 256>>>(b3w, b3u, b5w, b5u);
    }

    /* O1 = hidden @ Wo1^T — full corrections (classifier-facing) */
    gemm3<<<dim3(HDIM / GBN, NCROW / GBM), 256, GEMM_SMEM>>>(
        pHh, pHl, HDIM, pWoh, pWol, 2 * HDIM, pO1, HDIM, HDIM, HDIM);
    pw_relu<<<PW_BLOCKS, 256>>>(bout);

    cls_partial<<<dim3(N_OBJ / 32, C_CLS), 160>>>(wcls);
    cls_reduce<<<(N_OBJ * C_CLS + 255) / 256, 256>>>(bcls, out);
}

// round 15
// speedup vs baseline: 1.3570x; 1.0891x over previous
#include <cuda_runtime.h>
#include <cuda_fp16.h>
#include <math.h>

#define N_OBJ 256
#define C_CLS 151
#define HDIM  512
#define NCROW (N_OBJ * C_CLS)
#define KX    1536
#define CH    (C_CLS * HDIM)
#define DPAD  256

#define LO_SCALE     256.0f
#define LO_INV_SCALE 0.00390625f

/* ------------------- scratch: device globals (no allocs) ------------------ */
__device__ float g_hidden[(size_t)NCROW * HDIM];
__device__ half  g_Xh[(size_t)NCROW * KX];
__device__ float g_Y[(size_t)NCROW * KX];
__device__ float g_YS[(size_t)DPAD * KX];
__device__ float g_Z1[(size_t)N_OBJ * KX];
__device__ float g_Z2[(size_t)N_OBJ * KX];
__device__ float g_Hbar[N_OBJ * HDIM];
__device__ half  g_Hbh[N_OBJ * HDIM];
__device__ half  g_Hbl[N_OBJ * HDIM];
__device__ half  g_MSh[(size_t)DPAD * 1024];
__device__ half  g_MSl[(size_t)DPAD * 1024];
__device__ float g_cM1[C_CLS];
__device__ float g_cM2[C_CLS];
__device__ half  g_RHh[(size_t)NCROW * HDIM];
__device__ half  g_Hh[(size_t)NCROW * HDIM];
__device__ half  g_Hl[(size_t)NCROW * HDIM];
__device__ float g_U5[(size_t)NCROW * HDIM];
__device__ float g_O1[(size_t)NCROW * HDIM];
__device__ float g_S[CH];
__device__ float g_MS1[CH];
__device__ float g_MS2[CH];
__device__ half  g_Wch[(size_t)KX * KX];
__device__ half  g_Wcl[(size_t)KX * KX];
__device__ half  g_W5uh[HDIM * HDIM];
__device__ half  g_Woh[HDIM * 2 * HDIM];
__device__ half  g_Wol[HDIM * 2 * HDIM];
__device__ half  g_Ih[N_OBJ * HDIM];
__device__ half  g_Il[N_OBJ * HDIM];
__device__ float g_B2[N_OBJ * HDIM];
__device__ float g_Pcls[(size_t)C_CLS * N_OBJ * C_CLS];

/* ------------------------------ helpers ----------------------------------- */
__device__ __forceinline__ void split_store(float v, half* ph, half* pl)
{
    half hi = __float2half_rn(v);
    *ph = hi;
    *pl = __float2half_rn((v - __half2float(hi)) * LO_SCALE);
}

__device__ __forceinline__ unsigned smem_u32(const void* p)
{
    return (unsigned)__cvta_generic_to_shared(p);
}

__device__ __forceinline__ void ldsm4(unsigned* r, unsigned addr)
{
    asm volatile("ldmatrix.sync.aligned.m8n8.x4.shared.b16 {%0,%1,%2,%3},[%4];"
        : "=r"(r[0]), "=r"(r[1]), "=r"(r[2]), "=r"(r[3]) : "r"(addr));
}

__device__ __forceinline__ void mma16816(float* c, const unsigned* a, const unsigned* b)
{
    asm volatile("mma.sync.aligned.m16n8k16.row.col.f32.f16.f16.f32 "
        "{%0,%1,%2,%3},{%4,%5,%6,%7},{%8,%9},{%0,%1,%2,%3};"
        : "+f"(c[0]), "+f"(c[1]), "+f"(c[2]), "+f"(c[3])
        : "r"(a[0]), "r"(a[1]), "r"(a[2]), "r"(a[3]), "r"(b[0]), "r"(b[1]));
}

__device__ __forceinline__ void cp16(void* dst_smem, const void* src_gmem)
{
    unsigned s = smem_u32(dst_smem);
    asm volatile("cp.async.cg.shared.global [%0], [%1], 16;" :: "r"(s), "l"(src_gmem));
}

__device__ __forceinline__ void cp_commit()
{
    asm volatile("cp.async.commit_group;" ::: "memory");
}

__device__ __forceinline__ void cp_wait0()
{
    asm volatile("cp.async.wait_group 0;" ::: "memory");
}

/* ------------------------- weight concat + split --------------------------- */
__global__ void build_wcat(const float* __restrict__ w3w, const float* __restrict__ w3u,
                           const float* __restrict__ w4w, const float* __restrict__ w4u,
                           const float* __restrict__ w5w)
{
    int idx = blockIdx.x * blockDim.x + threadIdx.x;
    if (idx >= KX * KX) return;
    int o = idx / KX;
    int k = idx - o * KX;
    float v;
    if (o < 512) {
        v = (k < 1024) ? w3w[o * 1024 + k] : w3u[o * 512 + (k - 1024)];
    } else if (o < 1024) {
        int oo = o - 512;
        v = (k < 1024) ? w4w[oo * 1024 + k] : w4u[oo * 512 + (k - 1024)];
    } else {
        int oo = o - 1024;
        v = (k < 1024) ? w5w[oo * 1024 + k] : 0.0f;
    }
    split_store(v, &g_Wch[idx], &g_Wcl[idx]);
}

__global__ void split_f32(const float* __restrict__ src, half* __restrict__ dh,
                          half* __restrict__ dl, int n)
{
    int idx = blockIdx.x * blockDim.x + threadIdx.x;
    if (idx >= n) return;
    split_store(src[idx], &dh[idx], &dl[idx]);
}

__global__ void conv_f16(const float* __restrict__ src, half* __restrict__ dh, int n)
{
    int idx = blockIdx.x * blockDim.x + threadIdx.x;
    if (idx >= n) return;
    dh[idx] = __float2half_rn(src[idx]);
}

/* ------------------- init hidden[n][c][h] = input[n][h] ------------------- */
__global__ void init_hidden(const float* __restrict__ input)
{
    size_t idx = (size_t)blockIdx.x * blockDim.x + threadIdx.x;
    int h = (int)(idx & (HDIM - 1));
    size_t m = idx >> 9;
    int n = (int)(m / C_CLS);
    g_hidden[idx] = input[(size_t)n * HDIM + h];
}

/* -------------------- S[c][h] = sum_n hidden[n][c][h] --------------------- */
__global__ void colsum_kernel()
{
    int idx = blockIdx.x * blockDim.x + threadIdx.x;
    float s = 0.f;
    #pragma unroll 4
    for (int n = 0; n < N_OBJ; n++) s += g_hidden[(size_t)n * CH + idx];
    g_S[idx] = s;
}

/* ------------- Hbar[n][h] = mean_c hidden[n][c][h]  (+ hi/lo split) ------- */
__global__ void hbar_kernel()
{
    int idx = blockIdx.x * blockDim.x + threadIdx.x;
    int n = idx >> 9;
    int h = idx & (HDIM - 1);
    const float* p = g_hidden + (size_t)n * CH + h;
    float s = 0.f;
    for (int c = 0; c < C_CLS; c++) s += p[(size_t)c * HDIM];
    float hb = s * (1.0f / C_CLS);
    g_Hbar[idx] = hb;
    split_store(hb, &g_Hbh[idx], &g_Hbl[idx]);
}

/* ------------- cM1[d] = sum_c M[c][d] ; cM2[d] = sum_c M[d][c] ------------ */
__global__ void cm_kernel(const float* __restrict__ M)
{
    int d = blockIdx.x * blockDim.x + threadIdx.x;
    if (d >= C_CLS) return;
    float s1 = 0.f, s2 = 0.f;
    for (int c = 0; c < C_CLS; c++) {
        s1 += M[c * C_CLS + d];
        s2 += M[d * C_CLS + c];
    }
    g_cM1[d] = s1;
    g_cM2[d] = s2;
}

/* --------- MS1[d][h]=sum_c M[c][d]S[c][h] ; MS2[d][h]=sum_c M[d][c]S ------ */
__global__ void msprop_kernel(const float* __restrict__ M)
{
    int idx = blockIdx.x * blockDim.x + threadIdx.x;
    int d = idx / HDIM;
    int h = idx - d * HDIM;
    float s1 = 0.f, s2 = 0.f;
    for (int c = 0; c < C_CLS; c++) {
        float sv = g_S[c * HDIM + h];
        s1 += M[c * C_CLS + d] * sv;
        s2 += M[d * C_CLS + c] * sv;
    }
    g_MS1[idx] = s1;
    g_MS2[idx] = s2;
}

/* --- MScat padded split: MSh/MSl[d][k], d<DPAD, k<1024 --------------------- */
__global__ void ms_split_kernel()
{
    int idx = blockIdx.x * blockDim.x + threadIdx.x;
    int d = idx >> 10;
    int k = idx & 1023;
    float v = 0.f;
    if (d < C_CLS)
        v = (k < 512) ? g_MS1[d * HDIM + k] : g_MS2[d * HDIM + (k - 512)];
    split_store(v, &g_MSh[idx], &g_MSl[idx]);
}

/* --- t=0 shortcut: hidden==input per slot -> h - hbar == 0 -> X=[0|0|h] ---- */
__global__ void x0_kernel()
{
    size_t idx = (size_t)blockIdx.x * blockDim.x + threadIdx.x;  /* < NCROW*KX */
    size_t m = idx / KX;
    int k = (int)(idx - m * KX);
    float v = 0.f;
    if (k >= 1024) v = g_hidden[m * HDIM + (k - 1024)];
    g_Xh[idx] = __float2half_rn(v);
}

/* --- prop + X build: X[(n,d)] = [-a~1 | -a~2 | hidden]  (hi only) ---------- */
/* a~ = sum_c M * (h - hbar); 64 d-rows per block to reduce H re-reads.       */
#define P_DT 64
#define P_HT 64
__global__ __launch_bounds__(256) void prop_kernel(const float* __restrict__ M)
{
    __shared__ float Hs[8][P_HT];
    __shared__ float M1s[8][P_DT];
    __shared__ float M2s[8][P_DT];
    int n  = blockIdx.z;
    int d0 = blockIdx.y * P_DT;
    int h0 = blockIdx.x * P_HT;
    int tid = threadIdx.x;
    int hx = tid & 31;
    int ty = tid >> 5;
    float a1[8][2];
    float a2[8][2];
    #pragma unroll
    for (int i = 0; i < 8; i++) {
        a1[i][0] = 0.f; a1[i][1] = 0.f;
        a2[i][0] = 0.f; a2[i][1] = 0.f;
    }
    const float* Hn = g_hidden + (size_t)n * CH;
    const float* Hb = g_Hbar + (size_t)n * HDIM;

    for (int c0 = 0; c0 < C_CLS; c0 += 8) {
        #pragma unroll
        for (int l = 0; l < 2; l++) {
            int f = tid + l * 256;
            int cc = f >> 6;
            int hh = f & 63;
            int c = c0 + cc;
            Hs[cc][hh] = (c < C_CLS)
                ? (Hn[(size_t)c * HDIM + h0 + hh] - Hb[h0 + hh]) : 0.f;
        }
        #pragma unroll
        for (int l = 0; l < 2; l++) {
            int f = tid + l * 256;
            int cc = f >> 6;
            int dd = f & 63;
            int c = c0 + cc;
            int d = d0 + dd;
            bool ok = (c < C_CLS) && (d < C_CLS);
            M1s[cc][dd] = ok ? M[c * C_CLS + d] : 0.f;
            M2s[cc][dd] = ok ? M[d * C_CLS + c] : 0.f;
        }
        __syncthreads();
        #pragma unroll
        for (int cc = 0; cc < 8; cc++) {
            float hv0 = Hs[cc][hx];
            float hv1 = Hs[cc][hx + 32];
            #pragma unroll
            for (int i = 0; i < 8; i++) {
                float m1 = M1s[cc][ty * 8 + i];
                float m2 = M2s[cc][ty * 8 + i];
                a1[i][0] += m1 * hv0;
                a1[i][1] += m1 * hv1;
                a2[i][0] += m2 * hv0;
                a2[i][1] += m2 * hv1;
            }
        }
        __syncthreads();
    }
    #pragma unroll
    for (int i = 0; i < 8; i++) {
        int d = d0 + ty * 8 + i;
        if (d < C_CLS) {
            size_t r = (size_t)(n * C_CLS + d) * KX;
            #pragma unroll
            for (int q = 0; q < 2; q++) {
                int h = h0 + hx + q * 32;
                g_Xh[r + h]        = __float2half_rn(-a1[i][q]);
                g_Xh[r + 512 + h]  = __float2half_rn(-a2[i][q]);
                g_Xh[r + 1024 + h] = __float2half_rn(Hn[(size_t)d * HDIM + h]);
            }
        }
    }
}

/* ----------- tensor-core GEMM  C[m][n] = sum_k A[m][k] * B[n][k] ----------- */
#define GBM 128
#define GBN 128
#define GBK 32
#define SROW 40
#define SA_IDX(b, hl, r, c) (((((b) * 2 + (hl)) * GBM) + (r)) * SROW + (c))
#define SB_IDX(b, hl, r, c) (((((b) * 2 + (hl)) * GBN) + (r)) * SROW + (c))

__device__ __forceinline__ void gemm_load_stage(
    half* sA, half* sB, int s, int k0, int tid, int m0, int n0,
    const half* Ah, const half* Al, int lda,
    const half* Bh, const half* Bl, int ldb, bool corr)
{
    #pragma unroll
    for (int t = 0; t < 2; t++) {
        int idx = tid + t * 256;
        int row = idx >> 2;
        int ck  = (idx & 3) * 8;
        cp16(&sA[SA_IDX(s, 0, row, ck)], Ah + (size_t)(m0 + row) * lda + k0 + ck);
        cp16(&sB[SB_IDX(s, 0, row, ck)], Bh + (size_t)(n0 + row) * ldb + k0 + ck);
        if (corr) {
            cp16(&sA[SA_IDX(s, 1, row, ck)], Al + (size_t)(m0 + row) * lda + k0 + ck);
            cp16(&sB[SB_IDX(s, 1, row, ck)], Bl + (size_t)(n0 + row) * ldb + k0 + ck);
        }
    }
}

__global__ __launch_bounds__(256, 1) void gemm3(
    const half* __restrict__ Ah, const half* __restrict__ Al, int lda,
    const half* __restrict__ Bh, const half* __restrict__ Bl, int ldb,
    float* __restrict__ Cout, int ldc, int K, int KC)
{
    extern __shared__ half smem[];
    half* sA = smem;
    half* sB = smem + 2 * 2 * GBM * SROW;

    int tid = threadIdx.x;
    int warp = tid >> 5;
    int lane = tid & 31;
    int wm = warp >> 2;
    int wn = warp & 3;
    int m0 = blockIdx.y * GBM;
    int n0 = blockIdx.x * GBN;

    float acc[4][4][4];
    float accS[4][4][4];
    float acl[4][4][4];
    #pragma unroll
    for (int i = 0; i < 4; i++) {
        #pragma unroll
        for (int j = 0; j < 4; j++) {
            #pragma unroll
            for (int q = 0; q < 4; q++) {
                acc[i][j][q]  = 0.f;
                accS[i][j][q] = 0.f;
                acl[i][j][q]  = 0.f;
            }
        }
    }

    gemm_load_stage(sA, sB, 0, 0, tid, m0, n0, Ah, Al, lda, Bh, Bl, ldb, 0 < KC);
    cp_commit();

    int nit = K / GBK;
    for (int it = 0; it < nit; it++) {
        int cur = it & 1;
        bool corr = (it * GBK) < KC;
        cp_wait0();
        __syncthreads();
        if (it + 1 < nit) {
            gemm_load_stage(sA, sB, cur ^ 1, (it + 1) * GBK, tid, m0, n0,
                            Ah, Al, lda, Bh, Bl, ldb, ((it + 1) * GBK) < KC);
            cp_commit();
        }
        #pragma unroll
        for (int ks = 0; ks < 2; ks++) {
            int kk = ks * 16;
            unsigned bhf[2][4];
            unsigned blf[2][4];
            #pragma unroll
            for (int p = 0; p < 2; p++) {
                int nn = wn * 32 + p * 16 + ((lane >> 4) << 3) + (lane & 7);
                int kb = kk + (((lane >> 3) & 1) << 3);
                ldsm4(bhf[p], smem_u32(&sB[SB_IDX(cur, 0, nn, kb)]));
                if (corr)
                    ldsm4(blf[p], smem_u32(&sB[SB_IDX(cur, 1, nn, kb)]));
            }
            #pragma unroll
            for (int mf = 0; mf < 4; mf++) {
                int mm = wm * 64 + mf * 16 + (lane & 15);
                int ka = kk + ((lane >> 4) << 3);
                unsigned ahf[4];
                unsigned alf[4];
                ldsm4(ahf, smem_u32(&sA[SA_IDX(cur, 0, mm, ka)]));
                if (corr)
                    ldsm4(alf, smem_u32(&sA[SA_IDX(cur, 1, mm, ka)]));
                #pragma unroll
                for (int nf = 0; nf < 4; nf++)
                    mma16816(acc[mf][nf], ahf, &bhf[nf >> 1][(nf & 1) * 2]);
                if (corr) {
                    #pragma unroll
                    for (int nf = 0; nf < 4; nf++)
                        mma16816(acl[mf][nf], ahf, &blf[nf >> 1][(nf & 1) * 2]);
                    #pragma unroll
                    for (int nf = 0; nf < 4; nf++)
                        mma16816(acl[mf][nf], alf, &bhf[nf >> 1][(nf & 1) * 2]);
                }
            }
        }
        #pragma unroll
        for (int mf = 0; mf < 4; mf++) {
            #pragma unroll
            for (int nf = 0; nf < 4; nf++) {
                #pragma unroll
                for (int q = 0; q < 4; q++) {
                    accS[mf][nf][q] += acc[mf][nf][q];
                    acc[mf][nf][q] = 0.f;
                }
            }
        }
        __syncthreads();
    }

    int r = lane >> 2;
    int cb = (lane & 3) * 2;
    #pragma unroll
    for (int mf = 0; mf < 4; mf++) {
        #pragma unroll
        for (int nf = 0; nf < 4; nf++) {
            float* Cp = Cout + (size_t)(m0 + wm * 64 + mf * 16 + r) * ldc
                             + (n0 + wn * 32 + nf * 8 + cb);
            Cp[0] = accS[mf][nf][0] + acl[mf][nf][0] * LO_INV_SCALE;
            Cp[1] = accS[mf][nf][1] + acl[mf][nf][1] * LO_INV_SCALE;
            Cp += (size_t)8 * ldc;
            Cp[0] = accS[mf][nf][2] + acl[mf][nf][2] * LO_INV_SCALE;
            Cp[1] = accS[mf][nf][3] + acl[mf][nf][3] * LO_INV_SCALE;
        }
    }
}

/* ------------------------------ pointwise --------------------------------- */
__device__ __forceinline__ float sigmoidf_(float x)
{
    return 1.f / (1.f + expf(-x));
}

__global__ void pw_rv(const float* __restrict__ b4w, const float* __restrict__ b4u)
{
    size_t idx = (size_t)blockIdx.x * blockDim.x + threadIdx.x;
    int h = (int)(idx & (HDIM - 1));
    size_t m = idx >> 9;
    int n = (int)(m / C_CLS);
    int d = (int)(m - (size_t)n * C_CLS);
    size_t o = 512 + h;
    float pre = g_Y[m * KX + o] + g_YS[(size_t)d * KX + o]
              - g_cM1[d] * g_Z1[(size_t)n * KX + o]
              - g_cM2[d] * g_Z2[(size_t)n * KX + o]
              + b4w[h] + b4u[h];
    float rh = sigmoidf_(pre) * g_hidden[idx];
    g_RHh[idx] = __float2half_rn(rh);
}

__global__ void pw_update(const float* __restrict__ b3w, const float* __restrict__ b3u,
                          const float* __restrict__ b5w, const float* __restrict__ b5u)
{
    size_t idx = (size_t)blockIdx.x * blockDim.x + threadIdx.x;
    int h = (int)(idx & (HDIM - 1));
    size_t m = idx >> 9;
    int n = (int)(m / C_CLS);
    int d = (int)(m - (size_t)n * C_CLS);
    const float* ys = g_YS + (size_t)d * KX;
    const float* z1 = g_Z1 + (size_t)n * KX;
    const float* z2 = g_Z2 + (size_t)n * KX;
    float c1 = g_cM1[d];
    float c2 = g_cM2[d];
    float preZ = g_Y[m * KX + h] + ys[h] - c1 * z1[h] - c2 * z2[h]
               + b3w[h] + b3u[h];
    float preH = g_Y[m * KX + 1024 + h] + ys[1024 + h]
               - c1 * z1[1024 + h] - c2 * z2[1024 + h]
               + b5w[h] + g_U5[idx] + b5u[h];
    float z  = sigmoidf_(preZ);
    float hv = tanhf(preH);
    float hp = g_hidden[idx];
    float nh = (1.f - z) * hp + z * hv;
    g_hidden[idx] = nh;
    split_store(nh, &g_Hh[idx], &g_Hl[idx]);
}

__global__ void pw_relu(const float* __restrict__ bout)
{
    size_t idx = (size_t)blockIdx.x * blockDim.x + threadIdx.x;
    int h = (int)(idx & (HDIM - 1));
    size_t m = idx >> 9;
    int n = (int)(m / C_CLS);
    float v = g_O1[idx] + g_B2[n * HDIM + h] + bout[h];
    g_O1[idx] = v > 0.f ? v : 0.f;
}

/* --------------------- classifier: split-K over c ------------------------- */
__global__ __launch_bounds__(160) void cls_partial(const float* __restrict__ wcls)
{
    __shared__ float O1s[32][64];
    int nt = blockIdx.x;
    int ks = blockIdx.y;
    int j = threadIdx.x;
    float acc[32];
    #pragma unroll
    for (int nn = 0; nn < 32; nn++) acc[nn] = 0.f;

    for (int kb = 0; kb < 512; kb += 64) {
        for (int f = threadIdx.x; f < 32 * 64; f += 160) {
            int nn = f >> 6;
            int kk = f & 63;
            O1s[nn][kk] = g_O1[(size_t)(nt * 32 + nn) * CH + ks * 512 + kb + kk];
        }
        __syncthreads();
        if (j < C_CLS) {
            const float* wrow = wcls + (size_t)j * CH + ks * 512 + kb;
            #pragma unroll 4
            for (int kk = 0; kk < 64; kk += 4) {
                float4 w = *(const float4*)(wrow + kk);
                #pragma unroll
                for (int nn = 0; nn < 32; nn++) {
                    float4 o = *(const float4*)&O1s[nn][kk];
                    acc[nn] += w.x * o.x + w.y * o.y + w.z * o.z + w.w * o.w;
                }
            }
        }
        __syncthreads();
    }
    if (j < C_CLS) {
        #pragma unroll
        for (int nn = 0; nn < 32; nn++)
            g_Pcls[((size_t)ks * N_OBJ + nt * 32 + nn) * C_CLS + j] = acc[nn];
    }
}

__global__ void cls_reduce(const float* __restrict__ bcls, float* __restrict__ out)
{
    int idx = blockIdx.x * blockDim.x + threadIdx.x;
    if (idx >= N_OBJ * C_CLS) return;
    int n = idx / C_CLS;
    int j = idx - n * C_CLS;
    float s = bcls[j];
    for (int ks = 0; ks < C_CLS; ks++)
        s += g_Pcls[((size_t)ks * N_OBJ + n) * C_CLS + j];
    out[idx] = s;
}

/* --------------------------------------------------------------------------- */
extern "C" void kernel_launch(void* const* d_in, const int* in_sizes, int n_in,
                              void* d_out, int out_size)
{
    const float* input  = (const float*)d_in[0];
    const float* matrix = (const float*)d_in[1];
    const float* w3w = (const float*)d_in[2];
    const float* b3w = (const float*)d_in[3];
    const float* w3u = (const float*)d_in[4];
    const float* b3u = (const float*)d_in[5];
    const float* w4w = (const float*)d_in[6];
    const float* b4w = (const float*)d_in[7];
    const float* w4u = (const float*)d_in[8];
    const float* b4u = (const float*)d_in[9];
    const float* w5w = (const float*)d_in[10];
    const float* b5w = (const float*)d_in[11];
    const float* w5u = (const float*)d_in[12];
    const float* b5u = (const float*)d_in[13];
    const float* wout = (const float*)d_in[14];
    const float* bout = (const float*)d_in[15];
    const float* wcls = (const float*)d_in[16];
    const float* bcls = (const float*)d_in[17];
    float* out = (float*)d_out;

    void* tmp = 0;
    float* pY;
    float* pYS;
    float* pZ1;
    float* pZ2;
    float* pU5;
    float* pO1;
    float* pB2;
    half* pXh;
    half* pWch;
    half* pWcl;
    half* pRHh;
    half* pHh;
    half* pHl;
    half* pW5uh;
    half* pWoh;
    half* pWol;
    half* pIh;
    half* pIl;
    half* pMSh;
    half* pMSl;
    half* pHbh;
    half* pHbl;

    cudaGetSymbolAddress(&tmp, g_Y);     pY    = (float*)tmp;
    cudaGetSymbolAddress(&tmp, g_YS);    pYS   = (float*)tmp;
    cudaGetSymbolAddress(&tmp, g_Z1);    pZ1   = (float*)tmp;
    cudaGetSymbolAddress(&tmp, g_Z2);    pZ2   = (float*)tmp;
    cudaGetSymbolAddress(&tmp, g_U5);    pU5   = (float*)tmp;
    cudaGetSymbolAddress(&tmp, g_O1);    pO1   = (float*)tmp;
    cudaGetSymbolAddress(&tmp, g_B2);    pB2   = (float*)tmp;
    cudaGetSymbolAddress(&tmp, g_Xh);    pXh   = (half*)tmp;
    cudaGetSymbolAddress(&tmp, g_Wch);   pWch  = (half*)tmp;
    cudaGetSymbolAddress(&tmp, g_Wcl);   pWcl  = (half*)tmp;
    cudaGetSymbolAddress(&tmp, g_RHh);   pRHh  = (half*)tmp;
    cudaGetSymbolAddress(&tmp, g_Hh);    pHh   = (half*)tmp;
    cudaGetSymbolAddress(&tmp, g_Hl);    pHl   = (half*)tmp;
    cudaGetSymbolAddress(&tmp, g_W5uh);  pW5uh = (half*)tmp;
    cudaGetSymbolAddress(&tmp, g_Woh);   pWoh  = (half*)tmp;
    cudaGetSymbolAddress(&tmp, g_Wol);   pWol  = (half*)tmp;
    cudaGetSymbolAddress(&tmp, g_Ih);    pIh   = (half*)tmp;
    cudaGetSymbolAddress(&tmp, g_Il);    pIl   = (half*)tmp;
    cudaGetSymbolAddress(&tmp, g_MSh);   pMSh  = (half*)tmp;
    cudaGetSymbolAddress(&tmp, g_MSl);   pMSl  = (half*)tmp;
    cudaGetSymbolAddress(&tmp, g_Hbh);   pHbh  = (half*)tmp;
    cudaGetSymbolAddress(&tmp, g_Hbl);   pHbl  = (half*)tmp;

    const int GEMM_SMEM = 2 * 2 * (GBM + GBN) * SROW * (int)sizeof(half);
    cudaFuncSetAttribute(gemm3, cudaFuncAttributeMaxDynamicSharedMemorySize, GEMM_SMEM);

    const int PW_BLOCKS = (int)(((size_t)NCROW * HDIM) / 256);
    const int CH_BLOCKS = CH / 256;
    const int NH_BLOCKS = (N_OBJ * HDIM) / 256;

    build_wcat<<<(KX * KX + 255) / 256, 256>>>(w3w, w3u, w4w, w4u, w5w);
    split_f32<<<(HDIM * 2 * HDIM + 255) / 256, 256>>>(wout, pWoh, pWol,
                                                      HDIM * 2 * HDIM);
    split_f32<<<(N_OBJ * HDIM + 255) / 256, 256>>>(input, pIh, pIl,
                                                   N_OBJ * HDIM);
    /* B2 = input @ Wo2^T — full corrections (launch #3, profiled) */
    gemm3<<<dim3(HDIM / GBN, N_OBJ / GBM), 256, GEMM_SMEM>>>(
        pIh, pIl, HDIM, pWoh + 512, pWol + 512, 2 * HDIM, pB2, HDIM, HDIM, HDIM);
    conv_f16<<<(HDIM * HDIM + 255) / 256, 256>>>(w5u, pW5uh, HDIM * HDIM);
    cm_kernel<<<1, 256>>>(matrix);
    init_hidden<<<PW_BLOCKS, 256>>>(input);

    for (int t = 0; t < 3; t++) {
        colsum_kernel<<<CH_BLOCKS, 256>>>();
        msprop_kernel<<<CH_BLOCKS, 256>>>(matrix);
        hbar_kernel<<<NH_BLOCKS, 256>>>();
        ms_split_kernel<<<(DPAD * 1024) / 256, 256>>>();
        /* YS = MScat @ Wcat[:, :1024]^T — fp16x3 full corrections */
        gemm3<<<dim3(KX / GBN, DPAD / GBM), 256, GEMM_SMEM>>>(
            pMSh, pMSl, 1024, pWch, pWcl, KX, pYS, KX, 1024, 1024);
        /* Z1 = Hbar @ Wcat[:, 0:512]^T ; Z2 = Hbar @ Wcat[:, 512:1024]^T */
        gemm3<<<dim3(KX / GBN, N_OBJ / GBM), 256, GEMM_SMEM>>>(
            pHbh, pHbl, HDIM, pWch, pWcl, KX, pZ1, KX, HDIM, HDIM);
        gemm3<<<dim3(KX / GBN, N_OBJ / GBM), 256, GEMM_SMEM>>>(
            pHbh, pHbl, HDIM, pWch + 512, pWcl + 512, KX, pZ2, KX, HDIM, HDIM);
        if (t == 0) {
            /* hidden == input per class slot -> residual a~ is exactly 0 */
            x0_kernel<<<(int)(((size_t)NCROW * KX) / 256), 256>>>();
        } else {
            prop_kernel<<<dim3(HDIM / P_HT, (C_CLS + P_DT - 1) / P_DT, N_OBJ),
                          256>>>(matrix);
        }
        /* Yres[:, 0:1024] = X @ Wcat[0:1024]^T : hi-only, K=1536 */
        gemm3<<<dim3(1024 / GBN, NCROW / GBM), 256, GEMM_SMEM>>>(
            pXh, pXh, KX, pWch, pWch, KX, pY, KX, KX, 0);
        /* Yres[:, 1024:1536]: Wcat rows 1024.. are zero for k>=1024 -> K=1024 */
        gemm3<<<dim3(512 / GBN, NCROW / GBM), 256, GEMM_SMEM>>>(
            pXh, pXh, KX, pWch + (size_t)1024 * KX, pWch + (size_t)1024 * KX, KX,
            pY + 1024, KX, 1024, 0);
        pw_rv<<<PW_BLOCKS, 256>>>(b4w, b4u);
        /* U5 = (rv*h) @ W5u^T : hi-only */
        gemm3<<<dim3(HDIM / GBN, NCROW / GBM), 256, GEMM_SMEM>>>(
            pRHh, pRHh, HDIM, pW5uh, pW5uh, HDIM, pU5, HDIM, HDIM, 0);
        pw_update<<<PW_BLOCKS, 256>>>(b3w, b3u, b5w, b5u);
    }

    /* O1 = hidden @ Wo1^T — full corrections (classifier-facing) */
    gemm3<<<dim3(HDIM / GBN, NCROW / GBM), 256, GEMM_SMEM>>>(
        pHh, pHl, HDIM, pWoh, pWol, 2 * HDIM, pO1, HDIM, HDIM, HDIM);
    pw_relu<<<PW_BLOCKS, 256>>>(bout);

    cls_partial<<<dim3(N_OBJ / 32, C_CLS), 160>>>(wcls);
    cls_reduce<<<(N_OBJ * C_CLS + 255) / 256, 256>>>(bcls, out);
}

// round 16
// speedup vs baseline: 1.9323x; 1.4239x over previous
#include <cuda_runtime.h>
#include <cuda_fp16.h>
#include <math.h>

#define N_OBJ 256
#define C_CLS 151
#define HDIM  512
#define NCROW (N_OBJ * C_CLS)
#define KX    1536
#define CH    (C_CLS * HDIM)
#define DPAD  256

#define LO_SCALE     256.0f
#define LO_INV_SCALE 0.00390625f

/* ------------------- scratch: device globals (no allocs) ------------------ */
__device__ float g_hidden[(size_t)NCROW * HDIM];
__device__ half  g_Xh[(size_t)NCROW * KX];
__device__ float g_Y[(size_t)NCROW * KX];
__device__ float g_Y0[(size_t)N_OBJ * 1024];
__device__ float g_YS[(size_t)DPAD * KX];
__device__ float g_Z1[(size_t)N_OBJ * KX];
__device__ float g_Z2[(size_t)N_OBJ * KX];
__device__ float g_Hbar[N_OBJ * HDIM];
__device__ half  g_Hbh[N_OBJ * HDIM];
__device__ half  g_Hbl[N_OBJ * HDIM];
__device__ half  g_MSh[(size_t)DPAD * 1024];
__device__ half  g_MSl[(size_t)DPAD * 1024];
__device__ float g_cM1[C_CLS];
__device__ float g_cM2[C_CLS];
__device__ half  g_RHh[(size_t)NCROW * HDIM];
__device__ half  g_Hh[(size_t)NCROW * HDIM];
__device__ half  g_Hl[(size_t)NCROW * HDIM];
__device__ float g_U5[(size_t)NCROW * HDIM];
__device__ float g_O1[(size_t)NCROW * HDIM];
__device__ float g_S[CH];
__device__ float g_MS1[CH];
__device__ float g_MS2[CH];
__device__ half  g_Wch[(size_t)KX * KX];
__device__ half  g_Wcl[(size_t)KX * KX];
__device__ half  g_W5uh[HDIM * HDIM];
__device__ half  g_Woh[HDIM * 2 * HDIM];
__device__ half  g_Wol[HDIM * 2 * HDIM];
__device__ half  g_Ih[N_OBJ * HDIM];
__device__ half  g_Il[N_OBJ * HDIM];
__device__ float g_B2[N_OBJ * HDIM];
__device__ float g_Pcls[(size_t)C_CLS * N_OBJ * C_CLS];

/* ------------------------------ helpers ----------------------------------- */
__device__ __forceinline__ void split_store(float v, half* ph, half* pl)
{
    half hi = __float2half_rn(v);
    *ph = hi;
    *pl = __float2half_rn((v - __half2float(hi)) * LO_SCALE);
}

__device__ __forceinline__ unsigned smem_u32(const void* p)
{
    return (unsigned)__cvta_generic_to_shared(p);
}

__device__ __forceinline__ void ldsm4(unsigned* r, unsigned addr)
{
    asm volatile("ldmatrix.sync.aligned.m8n8.x4.shared.b16 {%0,%1,%2,%3},[%4];"
        : "=r"(r[0]), "=r"(r[1]), "=r"(r[2]), "=r"(r[3]) : "r"(addr));
}

__device__ __forceinline__ void mma16816(float* c, const unsigned* a, const unsigned* b)
{
    asm volatile("mma.sync.aligned.m16n8k16.row.col.f32.f16.f16.f32 "
        "{%0,%1,%2,%3},{%4,%5,%6,%7},{%8,%9},{%0,%1,%2,%3};"
        : "+f"(c[0]), "+f"(c[1]), "+f"(c[2]), "+f"(c[3])
        : "r"(a[0]), "r"(a[1]), "r"(a[2]), "r"(a[3]), "r"(b[0]), "r"(b[1]));
}

__device__ __forceinline__ void cp16(void* dst_smem, const void* src_gmem)
{
    unsigned s = smem_u32(dst_smem);
    asm volatile("cp.async.cg.shared.global [%0], [%1], 16;" :: "r"(s), "l"(src_gmem));
}

__device__ __forceinline__ void cp_commit()
{
    asm volatile("cp.async.commit_group;" ::: "memory");
}

__device__ __forceinline__ void cp_wait0()
{
    asm volatile("cp.async.wait_group 0;" ::: "memory");
}

/* ------------------------- weight concat + split --------------------------- */
__global__ void build_wcat(const float* __restrict__ w3w, const float* __restrict__ w3u,
                           const float* __restrict__ w4w, const float* __restrict__ w4u,
                           const float* __restrict__ w5w)
{
    int idx = blockIdx.x * blockDim.x + threadIdx.x;
    if (idx >= KX * KX) return;
    int o = idx / KX;
    int k = idx - o * KX;
    float v;
    if (o < 512) {
        v = (k < 1024) ? w3w[o * 1024 + k] : w3u[o * 512 + (k - 1024)];
    } else if (o < 1024) {
        int oo = o - 512;
        v = (k < 1024) ? w4w[oo * 1024 + k] : w4u[oo * 512 + (k - 1024)];
    } else {
        int oo = o - 1024;
        v = (k < 1024) ? w5w[oo * 1024 + k] : 0.0f;
    }
    split_store(v, &g_Wch[idx], &g_Wcl[idx]);
}

__global__ void split_f32(const float* __restrict__ src, half* __restrict__ dh,
                          half* __restrict__ dl, int n)
{
    int idx = blockIdx.x * blockDim.x + threadIdx.x;
    if (idx >= n) return;
    split_store(src[idx], &dh[idx], &dl[idx]);
}

__global__ void conv_f16(const float* __restrict__ src, half* __restrict__ dh, int n)
{
    int idx = blockIdx.x * blockDim.x + threadIdx.x;
    if (idx >= n) return;
    dh[idx] = __float2half_rn(src[idx]);
}

/* ------------------- init hidden[n][c][h] = input[n][h] ------------------- */
__global__ void init_hidden(const float* __restrict__ input)
{
    size_t idx = (size_t)blockIdx.x * blockDim.x + threadIdx.x;
    int h = (int)(idx & (HDIM - 1));
    size_t m = idx >> 9;
    int n = (int)(m / C_CLS);
    g_hidden[idx] = input[(size_t)n * HDIM + h];
}

/* -------------------- S[c][h] = sum_n hidden[n][c][h] --------------------- */
__global__ void colsum_kernel()
{
    int idx = blockIdx.x * blockDim.x + threadIdx.x;
    float s = 0.f;
    #pragma unroll 4
    for (int n = 0; n < N_OBJ; n++) s += g_hidden[(size_t)n * CH + idx];
    g_S[idx] = s;
}

/* ------------- Hbar[n][h] = mean_c hidden[n][c][h]  (+ hi/lo split) ------- */
__global__ void hbar_kernel()
{
    int idx = blockIdx.x * blockDim.x + threadIdx.x;
    int n = idx >> 9;
    int h = idx & (HDIM - 1);
    const float* p = g_hidden + (size_t)n * CH + h;
    float s = 0.f;
    for (int c = 0; c < C_CLS; c++) s += p[(size_t)c * HDIM];
    float hb = s * (1.0f / C_CLS);
    g_Hbar[idx] = hb;
    split_store(hb, &g_Hbh[idx], &g_Hbl[idx]);
}

/* ------------- cM1[d] = sum_c M[c][d] ; cM2[d] = sum_c M[d][c] ------------ */
__global__ void cm_kernel(const float* __restrict__ M)
{
    int d = blockIdx.x * blockDim.x + threadIdx.x;
    if (d >= C_CLS) return;
    float s1 = 0.f, s2 = 0.f;
    for (int c = 0; c < C_CLS; c++) {
        s1 += M[c * C_CLS + d];
        s2 += M[d * C_CLS + c];
    }
    g_cM1[d] = s1;
    g_cM2[d] = s2;
}

/* --------- MS1[d][h]=sum_c M[c][d]S[c][h] ; MS2[d][h]=sum_c M[d][c]S ------ */
__global__ void msprop_kernel(const float* __restrict__ M)
{
    int idx = blockIdx.x * blockDim.x + threadIdx.x;
    int d = idx / HDIM;
    int h = idx - d * HDIM;
    float s1 = 0.f, s2 = 0.f;
    for (int c = 0; c < C_CLS; c++) {
        float sv = g_S[c * HDIM + h];
        s1 += M[c * C_CLS + d] * sv;
        s2 += M[d * C_CLS + c] * sv;
    }
    g_MS1[idx] = s1;
    g_MS2[idx] = s2;
}

/* --- MScat padded split: MSh/MSl[d][k], d<DPAD, k<1024 --------------------- */
__global__ void ms_split_kernel()
{
    int idx = blockIdx.x * blockDim.x + threadIdx.x;
    int d = idx >> 10;
    int k = idx & 1023;
    float v = 0.f;
    if (d < C_CLS)
        v = (k < 512) ? g_MS1[d * HDIM + k] : g_MS2[d * HDIM + (k - 512)];
    split_store(v, &g_MSh[idx], &g_MSl[idx]);
}

/* --- prop + X build: X[(n,d)] = [-a~1 | -a~2 | hidden]  (hi only) ---------- */
#define P_DT 64
#define P_HT 64
__global__ __launch_bounds__(256) void prop_kernel(const float* __restrict__ M)
{
    __shared__ float Hs[8][P_HT];
    __shared__ float M1s[8][P_DT];
    __shared__ float M2s[8][P_DT];
    int n  = blockIdx.z;
    int d0 = blockIdx.y * P_DT;
    int h0 = blockIdx.x * P_HT;
    int tid = threadIdx.x;
    int hx = tid & 31;
    int ty = tid >> 5;
    float a1[8][2];
    float a2[8][2];
    #pragma unroll
    for (int i = 0; i < 8; i++) {
        a1[i][0] = 0.f; a1[i][1] = 0.f;
        a2[i][0] = 0.f; a2[i][1] = 0.f;
    }
    const float* Hn = g_hidden + (size_t)n * CH;
    const float* Hb = g_Hbar + (size_t)n * HDIM;

    for (int c0 = 0; c0 < C_CLS; c0 += 8) {
        #pragma unroll
        for (int l = 0; l < 2; l++) {
            int f = tid + l * 256;
            int cc = f >> 6;
            int hh = f & 63;
            int c = c0 + cc;
            Hs[cc][hh] = (c < C_CLS)
                ? (Hn[(size_t)c * HDIM + h0 + hh] - Hb[h0 + hh]) : 0.f;
        }
        #pragma unroll
        for (int l = 0; l < 2; l++) {
            int f = tid + l * 256;
            int cc = f >> 6;
            int dd = f & 63;
            int c = c0 + cc;
            int d = d0 + dd;
            bool ok = (c < C_CLS) && (d < C_CLS);
            M1s[cc][dd] = ok ? M[c * C_CLS + d] : 0.f;
            M2s[cc][dd] = ok ? M[d * C_CLS + c] : 0.f;
        }
        __syncthreads();
        #pragma unroll
        for (int cc = 0; cc < 8; cc++) {
            float hv0 = Hs[cc][hx];
            float hv1 = Hs[cc][hx + 32];
            #pragma unroll
            for (int i = 0; i < 8; i++) {
                float m1 = M1s[cc][ty * 8 + i];
                float m2 = M2s[cc][ty * 8 + i];
                a1[i][0] += m1 * hv0;
                a1[i][1] += m1 * hv1;
                a2[i][0] += m2 * hv0;
                a2[i][1] += m2 * hv1;
            }
        }
        __syncthreads();
    }
    #pragma unroll
    for (int i = 0; i < 8; i++) {
        int d = d0 + ty * 8 + i;
        if (d < C_CLS) {
            size_t r = (size_t)(n * C_CLS + d) * KX;
            #pragma unroll
            for (int q = 0; q < 2; q++) {
                int h = h0 + hx + q * 32;
                g_Xh[r + h]        = __float2half_rn(-a1[i][q]);
                g_Xh[r + 512 + h]  = __float2half_rn(-a2[i][q]);
                g_Xh[r + 1024 + h] = __float2half_rn(Hn[(size_t)d * HDIM + h]);
            }
        }
    }
}

/* --------- full-precision tensor GEMM (3-product split + drain) ------------ */
#define GBM 128
#define GBN 128
#define GBK 32
#define SROW 40
#define SA_IDX(b, hl, r, c) (((((b) * 2 + (hl)) * GBM) + (r)) * SROW + (c))
#define SB_IDX(b, hl, r, c) (((((b) * 2 + (hl)) * GBN) + (r)) * SROW + (c))

__device__ __forceinline__ void gemm_load_stage(
    half* sA, half* sB, int s, int k0, int tid, int m0, int n0,
    const half* Ah, const half* Al, int lda,
    const half* Bh, const half* Bl, int ldb, bool corr)
{
    #pragma unroll
    for (int t = 0; t < 2; t++) {
        int idx = tid + t * 256;
        int row = idx >> 2;
        int ck  = (idx & 3) * 8;
        cp16(&sA[SA_IDX(s, 0, row, ck)], Ah + (size_t)(m0 + row) * lda + k0 + ck);
        cp16(&sB[SB_IDX(s, 0, row, ck)], Bh + (size_t)(n0 + row) * ldb + k0 + ck);
        if (corr) {
            cp16(&sA[SA_IDX(s, 1, row, ck)], Al + (size_t)(m0 + row) * lda + k0 + ck);
            cp16(&sB[SB_IDX(s, 1, row, ck)], Bl + (size_t)(n0 + row) * ldb + k0 + ck);
        }
    }
}

__global__ __launch_bounds__(256, 1) void gemm3(
    const half* __restrict__ Ah, const half* __restrict__ Al, int lda,
    const half* __restrict__ Bh, const half* __restrict__ Bl, int ldb,
    float* __restrict__ Cout, int ldc, int K, int KC)
{
    extern __shared__ half smem[];
    half* sA = smem;
    half* sB = smem + 2 * 2 * GBM * SROW;

    int tid = threadIdx.x;
    int warp = tid >> 5;
    int lane = tid & 31;
    int wm = warp >> 2;
    int wn = warp & 3;
    int m0 = blockIdx.y * GBM;
    int n0 = blockIdx.x * GBN;

    float acc[4][4][4];
    float accS[4][4][4];
    float acl[4][4][4];
    #pragma unroll
    for (int i = 0; i < 4; i++) {
        #pragma unroll
        for (int j = 0; j < 4; j++) {
            #pragma unroll
            for (int q = 0; q < 4; q++) {
                acc[i][j][q]  = 0.f;
                accS[i][j][q] = 0.f;
                acl[i][j][q]  = 0.f;
            }
        }
    }

    gemm_load_stage(sA, sB, 0, 0, tid, m0, n0, Ah, Al, lda, Bh, Bl, ldb, 0 < KC);
    cp_commit();

    int nit = K / GBK;
    for (int it = 0; it < nit; it++) {
        int cur = it & 1;
        bool corr = (it * GBK) < KC;
        cp_wait0();
        __syncthreads();
        if (it + 1 < nit) {
            gemm_load_stage(sA, sB, cur ^ 1, (it + 1) * GBK, tid, m0, n0,
                            Ah, Al, lda, Bh, Bl, ldb, ((it + 1) * GBK) < KC);
            cp_commit();
        }
        #pragma unroll
        for (int ks = 0; ks < 2; ks++) {
            int kk = ks * 16;
            unsigned bhf[2][4];
            unsigned blf[2][4];
            #pragma unroll
            for (int p = 0; p < 2; p++) {
                int nn = wn * 32 + p * 16 + ((lane >> 4) << 3) + (lane & 7);
                int kb = kk + (((lane >> 3) & 1) << 3);
                ldsm4(bhf[p], smem_u32(&sB[SB_IDX(cur, 0, nn, kb)]));
                if (corr)
                    ldsm4(blf[p], smem_u32(&sB[SB_IDX(cur, 1, nn, kb)]));
            }
            #pragma unroll
            for (int mf = 0; mf < 4; mf++) {
                int mm = wm * 64 + mf * 16 + (lane & 15);
                int ka = kk + ((lane >> 4) << 3);
                unsigned ahf[4];
                unsigned alf[4];
                ldsm4(ahf, smem_u32(&sA[SA_IDX(cur, 0, mm, ka)]));
                if (corr)
                    ldsm4(alf, smem_u32(&sA[SA_IDX(cur, 1, mm, ka)]));
                #pragma unroll
                for (int nf = 0; nf < 4; nf++)
                    mma16816(acc[mf][nf], ahf, &bhf[nf >> 1][(nf & 1) * 2]);
                if (corr) {
                    #pragma unroll
                    for (int nf = 0; nf < 4; nf++)
                        mma16816(acl[mf][nf], ahf, &blf[nf >> 1][(nf & 1) * 2]);
                    #pragma unroll
                    for (int nf = 0; nf < 4; nf++)
                        mma16816(acl[mf][nf], alf, &bhf[nf >> 1][(nf & 1) * 2]);
                }
            }
        }
        #pragma unroll
        for (int mf = 0; mf < 4; mf++) {
            #pragma unroll
            for (int nf = 0; nf < 4; nf++) {
                #pragma unroll
                for (int q = 0; q < 4; q++) {
                    accS[mf][nf][q] += acc[mf][nf][q];
                    acc[mf][nf][q] = 0.f;
                }
            }
        }
        __syncthreads();
    }

    int r = lane >> 2;
    int cb = (lane & 3) * 2;
    #pragma unroll
    for (int mf = 0; mf < 4; mf++) {
        #pragma unroll
        for (int nf = 0; nf < 4; nf++) {
            float* Cp = Cout + (size_t)(m0 + wm * 64 + mf * 16 + r) * ldc
                             + (n0 + wn * 32 + nf * 8 + cb);
            Cp[0] = accS[mf][nf][0] + acl[mf][nf][0] * LO_INV_SCALE;
            Cp[1] = accS[mf][nf][1] + acl[mf][nf][1] * LO_INV_SCALE;
            Cp += (size_t)8 * ldc;
            Cp[0] = accS[mf][nf][2] + acl[mf][nf][2] * LO_INV_SCALE;
            Cp[1] = accS[mf][nf][3] + acl[mf][nf][3] * LO_INV_SCALE;
        }
    }
}

/* --------- lean hi-only tensor GEMM: 2 CTAs/SM, no drain -------------------- */
/* Valid when operand magnitudes are O(1): RZ-accumulate bias ~K*2^-25 << fp16 */
/* input rounding. smem = 40KB, regs capped at 128 by launch_bounds(256,2).   */
#define S1A_IDX(b, r, c) ((((b) * GBM) + (r)) * SROW + (c))
#define S1B_IDX(b, r, c) ((((b) * GBN) + (r)) * SROW + (c))

__device__ __forceinline__ void gemm1_load_stage(
    half* sA, half* sB, int s, int k0, int tid, int m0, int n0,
    const half* Ah, int lda, const half* Bh, int ldb)
{
    #pragma unroll
    for (int t = 0; t < 2; t++) {
        int idx = tid + t * 256;
        int row = idx >> 2;
        int ck  = (idx & 3) * 8;
        cp16(&sA[S1A_IDX(s, row, ck)], Ah + (size_t)(m0 + row) * lda + k0 + ck);
        cp16(&sB[S1B_IDX(s, row, ck)], Bh + (size_t)(n0 + row) * ldb + k0 + ck);
    }
}

__global__ __launch_bounds__(256, 2) void gemm1(
    const half* __restrict__ Ah, int lda,
    const half* __restrict__ Bh, int ldb,
    float* __restrict__ Cout, int ldc, int K)
{
    extern __shared__ half smem[];
    half* sA = smem;
    half* sB = smem + 2 * GBM * SROW;

    int tid = threadIdx.x;
    int warp = tid >> 5;
    int lane = tid & 31;
    int wm = warp >> 2;
    int wn = warp & 3;
    int m0 = blockIdx.y * GBM;
    int n0 = blockIdx.x * GBN;

    float acc[4][4][4];
    #pragma unroll
    for (int i = 0; i < 4; i++) {
        #pragma unroll
        for (int j = 0; j < 4; j++) {
            acc[i][j][0] = 0.f;
            acc[i][j][1] = 0.f;
            acc[i][j][2] = 0.f;
            acc[i][j][3] = 0.f;
        }
    }

    gemm1_load_stage(sA, sB, 0, 0, tid, m0, n0, Ah, lda, Bh, ldb);
    cp_commit();

    int nit = K / GBK;
    for (int it = 0; it < nit; it++) {
        int cur = it & 1;
        cp_wait0();
        __syncthreads();
        if (it + 1 < nit) {
            gemm1_load_stage(sA, sB, cur ^ 1, (it + 1) * GBK, tid, m0, n0,
                             Ah, lda, Bh, ldb);
            cp_commit();
        }
        #pragma unroll
        for (int ks = 0; ks < 2; ks++) {
            int kk = ks * 16;
            unsigned bhf[2][4];
            #pragma unroll
            for (int p = 0; p < 2; p++) {
                int nn = wn * 32 + p * 16 + ((lane >> 4) << 3) + (lane & 7);
                int kb = kk + (((lane >> 3) & 1) << 3);
                ldsm4(bhf[p], smem_u32(&sB[S1B_IDX(cur, nn, kb)]));
            }
            #pragma unroll
            for (int mf = 0; mf < 4; mf++) {
                int mm = wm * 64 + mf * 16 + (lane & 15);
                int ka = kk + ((lane >> 4) << 3);
                unsigned ahf[4];
                ldsm4(ahf, smem_u32(&sA[S1A_IDX(cur, mm, ka)]));
                #pragma unroll
                for (int nf = 0; nf < 4; nf++)
                    mma16816(acc[mf][nf], ahf, &bhf[nf >> 1][(nf & 1) * 2]);
            }
        }
        __syncthreads();
    }

    int r = lane >> 2;
    int cb = (lane & 3) * 2;
    #pragma unroll
    for (int mf = 0; mf < 4; mf++) {
        #pragma unroll
        for (int nf = 0; nf < 4; nf++) {
            float* Cp = Cout + (size_t)(m0 + wm * 64 + mf * 16 + r) * ldc
                             + (n0 + wn * 32 + nf * 8 + cb);
            Cp[0] = acc[mf][nf][0];
            Cp[1] = acc[mf][nf][1];
            Cp += (size_t)8 * ldc;
            Cp[0] = acc[mf][nf][2];
            Cp[1] = acc[mf][nf][3];
        }
    }
}

/* ------------------------------ pointwise --------------------------------- */
__device__ __forceinline__ float sigmoidf_(float x)
{
    return 1.f / (1.f + expf(-x));
}

__global__ void pw_rv(const float* __restrict__ b4w, const float* __restrict__ b4u,
                      int t0)
{
    size_t idx = (size_t)blockIdx.x * blockDim.x + threadIdx.x;
    int h = (int)(idx & (HDIM - 1));
    size_t m = idx >> 9;
    int n = (int)(m / C_CLS);
    int d = (int)(m - (size_t)n * C_CLS);
    size_t o = 512 + h;
    float yv = t0 ? g_Y0[(size_t)n * 1024 + o] : g_Y[m * KX + o];
    float pre = yv + g_YS[(size_t)d * KX + o]
              - g_cM1[d] * g_Z1[(size_t)n * KX + o]
              - g_cM2[d] * g_Z2[(size_t)n * KX + o]
              + b4w[h] + b4u[h];
    float rh = sigmoidf_(pre) * g_hidden[idx];
    g_RHh[idx] = __float2half_rn(rh);
}

__global__ void pw_update(const float* __restrict__ b3w, const float* __restrict__ b3u,
                          const float* __restrict__ b5w, const float* __restrict__ b5u,
                          int t0)
{
    size_t idx = (size_t)blockIdx.x * blockDim.x + threadIdx.x;
    int h = (int)(idx & (HDIM - 1));
    size_t m = idx >> 9;
    int n = (int)(m / C_CLS);
    int d = (int)(m - (size_t)n * C_CLS);
    const float* ys = g_YS + (size_t)d * KX;
    const float* z1 = g_Z1 + (size_t)n * KX;
    const float* z2 = g_Z2 + (size_t)n * KX;
    float c1 = g_cM1[d];
    float c2 = g_cM2[d];
    float y1 = t0 ? g_Y0[(size_t)n * 1024 + h] : g_Y[m * KX + h];
    float y3 = t0 ? 0.f : g_Y[m * KX + 1024 + h];
    float preZ = y1 + ys[h] - c1 * z1[h] - c2 * z2[h] + b3w[h] + b3u[h];
    float preH = y3 + ys[1024 + h] - c1 * z1[1024 + h] - c2 * z2[1024 + h]
               + b5w[h] + g_U5[idx] + b5u[h];
    float z  = sigmoidf_(preZ);
    float hv = tanhf(preH);
    float hp = g_hidden[idx];
    float nh = (1.f - z) * hp + z * hv;
    g_hidden[idx] = nh;
    split_store(nh, &g_Hh[idx], &g_Hl[idx]);
}

__global__ void pw_relu(const float* __restrict__ bout)
{
    size_t idx = (size_t)blockIdx.x * blockDim.x + threadIdx.x;
    int h = (int)(idx & (HDIM - 1));
    size_t m = idx >> 9;
    int n = (int)(m / C_CLS);
    float v = g_O1[idx] + g_B2[n * HDIM + h] + bout[h];
    g_O1[idx] = v > 0.f ? v : 0.f;
}

/* --------------------- classifier: split-K over c ------------------------- */
__global__ __launch_bounds__(160) void cls_partial(const float* __restrict__ wcls)
{
    __shared__ float O1s[32][64];
    int nt = blockIdx.x;
    int ks = blockIdx.y;
    int j = threadIdx.x;
    float acc[32];
    #pragma unroll
    for (int nn = 0; nn < 32; nn++) acc[nn] = 0.f;

    for (int kb = 0; kb < 512; kb += 64) {
        for (int f = threadIdx.x; f < 32 * 64; f += 160) {
            int nn = f >> 6;
            int kk = f & 63;
            O1s[nn][kk] = g_O1[(size_t)(nt * 32 + nn) * CH + ks * 512 + kb + kk];
        }
        __syncthreads();
        if (j < C_CLS) {
            const float* wrow = wcls + (size_t)j * CH + ks * 512 + kb;
            #pragma unroll 4
            for (int kk = 0; kk < 64; kk += 4) {
                float4 w = *(const float4*)(wrow + kk);
                #pragma unroll
                for (int nn = 0; nn < 32; nn++) {
                    float4 o = *(const float4*)&O1s[nn][kk];
                    acc[nn] += w.x * o.x + w.y * o.y + w.z * o.z + w.w * o.w;
                }
            }
        }
        __syncthreads();
    }
    if (j < C_CLS) {
        #pragma unroll
        for (int nn = 0; nn < 32; nn++)
            g_Pcls[((size_t)ks * N_OBJ + nt * 32 + nn) * C_CLS + j] = acc[nn];
    }
}

__global__ void cls_reduce(const float* __restrict__ bcls, float* __restrict__ out)
{
    int idx = blockIdx.x * blockDim.x + threadIdx.x;
    if (idx >= N_OBJ * C_CLS) return;
    int n = idx / C_CLS;
    int j = idx - n * C_CLS;
    float s = bcls[j];
    for (int ks = 0; ks < C_CLS; ks++)
        s += g_Pcls[((size_t)ks * N_OBJ + n) * C_CLS + j];
    out[idx] = s;
}

/* --------------------------------------------------------------------------- */
extern "C" void kernel_launch(void* const* d_in, const int* in_sizes, int n_in,
                              void* d_out, int out_size)
{
    const float* input  = (const float*)d_in[0];
    const float* matrix = (const float*)d_in[1];
    const float* w3w = (const float*)d_in[2];
    const float* b3w = (const float*)d_in[3];
    const float* w3u = (const float*)d_in[4];
    const float* b3u = (const float*)d_in[5];
    const float* w4w = (const float*)d_in[6];
    const float* b4w = (const float*)d_in[7];
    const float* w4u = (const float*)d_in[8];
    const float* b4u = (const float*)d_in[9];
    const float* w5w = (const float*)d_in[10];
    const float* b5w = (const float*)d_in[11];
    const float* w5u = (const float*)d_in[12];
    const float* b5u = (const float*)d_in[13];
    const float* wout = (const float*)d_in[14];
    const float* bout = (const float*)d_in[15];
    const float* wcls = (const float*)d_in[16];
    const float* bcls = (const float*)d_in[17];
    float* out = (float*)d_out;

    void* tmp = 0;
    float* pY;
    float* pY0;
    float* pYS;
    float* pZ1;
    float* pZ2;
    float* pU5;
    float* pO1;
    float* pB2;
    half* pXh;
    half* pWch;
    half* pWcl;
    half* pRHh;
    half* pHh;
    half* pHl;
    half* pW5uh;
    half* pWoh;
    half* pWol;
    half* pIh;
    half* pIl;
    half* pMSh;
    half* pMSl;
    half* pHbh;
    half* pHbl;

    cudaGetSymbolAddress(&tmp, g_Y);     pY    = (float*)tmp;
    cudaGetSymbolAddress(&tmp, g_Y0);    pY0   = (float*)tmp;
    cudaGetSymbolAddress(&tmp, g_YS);    pYS   = (float*)tmp;
    cudaGetSymbolAddress(&tmp, g_Z1);    pZ1   = (float*)tmp;
    cudaGetSymbolAddress(&tmp, g_Z2);    pZ2   = (float*)tmp;
    cudaGetSymbolAddress(&tmp, g_U5);    pU5   = (float*)tmp;
    cudaGetSymbolAddress(&tmp, g_O1);    pO1   = (float*)tmp;
    cudaGetSymbolAddress(&tmp, g_B2);    pB2   = (float*)tmp;
    cudaGetSymbolAddress(&tmp, g_Xh);    pXh   = (half*)tmp;
    cudaGetSymbolAddress(&tmp, g_Wch);   pWch  = (half*)tmp;
    cudaGetSymbolAddress(&tmp, g_Wcl);   pWcl  = (half*)tmp;
    cudaGetSymbolAddress(&tmp, g_RHh);   pRHh  = (half*)tmp;
    cudaGetSymbolAddress(&tmp, g_Hh);    pHh   = (half*)tmp;
    cudaGetSymbolAddress(&tmp, g_Hl);    pHl   = (half*)tmp;
    cudaGetSymbolAddress(&tmp, g_W5uh);  pW5uh = (half*)tmp;
    cudaGetSymbolAddress(&tmp, g_Woh);   pWoh  = (half*)tmp;
    cudaGetSymbolAddress(&tmp, g_Wol);   pWol  = (half*)tmp;
    cudaGetSymbolAddress(&tmp, g_Ih);    pIh   = (half*)tmp;
    cudaGetSymbolAddress(&tmp, g_Il);    pIl   = (half*)tmp;
    cudaGetSymbolAddress(&tmp, g_MSh);   pMSh  = (half*)tmp;
    cudaGetSymbolAddress(&tmp, g_MSl);   pMSl  = (half*)tmp;
    cudaGetSymbolAddress(&tmp, g_Hbh);   pHbh  = (half*)tmp;
    cudaGetSymbolAddress(&tmp, g_Hbl);   pHbl  = (half*)tmp;

    const int GEMM_SMEM  = 2 * 2 * (GBM + GBN) * SROW * (int)sizeof(half); /* 81920 */
    const int GEMM1_SMEM = 2 * (GBM + GBN) * SROW * (int)sizeof(half);     /* 40960 */
    cudaFuncSetAttribute(gemm3, cudaFuncAttributeMaxDynamicSharedMemorySize, GEMM_SMEM);
    cudaFuncSetAttribute(gemm1, cudaFuncAttributeMaxDynamicSharedMemorySize, GEMM1_SMEM);

    const int PW_BLOCKS = (int)(((size_t)NCROW * HDIM) / 256);
    const int CH_BLOCKS = CH / 256;
    const int NH_BLOCKS = (N_OBJ * HDIM) / 256;

    build_wcat<<<(KX * KX + 255) / 256, 256>>>(w3w, w3u, w4w, w4u, w5w);
    split_f32<<<(HDIM * 2 * HDIM + 255) / 256, 256>>>(wout, pWoh, pWol,
                                                      HDIM * 2 * HDIM);
    split_f32<<<(N_OBJ * HDIM + 255) / 256, 256>>>(input, pIh, pIl,
                                                   N_OBJ * HDIM);
    /* B2 = input @ Wo2^T — full corrections (launch #3, profiled) */
    gemm3<<<dim3(HDIM / GBN, N_OBJ / GBM), 256, GEMM_SMEM>>>(
        pIh, pIl, HDIM, pWoh + 512, pWol + 512, 2 * HDIM, pB2, HDIM, HDIM, HDIM);
    conv_f16<<<(HDIM * HDIM + 255) / 256, 256>>>(w5u, pW5uh, HDIM * HDIM);
    cm_kernel<<<1, 256>>>(matrix);
    init_hidden<<<PW_BLOCKS, 256>>>(input);

    /* t=0 Y shortcut: Y0[n, 0:1024] = input @ W34u^T (Wcat cols 1024:1536) */
    gemm3<<<dim3(1024 / GBN, N_OBJ / GBM), 256, GEMM_SMEM>>>(
        pIh, pIl, HDIM, pWch + 1024, pWcl + 1024, KX, pY0, 1024, HDIM, HDIM);

    for (int t = 0; t < 3; t++) {
        colsum_kernel<<<CH_BLOCKS, 256>>>();
        msprop_kernel<<<CH_BLOCKS, 256>>>(matrix);
        hbar_kernel<<<NH_BLOCKS, 256>>>();
        ms_split_kernel<<<(DPAD * 1024) / 256, 256>>>();
        /* YS = MScat @ Wcat[:, :1024]^T — fp16x3 full corrections */
        gemm3<<<dim3(KX / GBN, DPAD / GBM), 256, GEMM_SMEM>>>(
            pMSh, pMSl, 1024, pWch, pWcl, KX, pYS, KX, 1024, 1024);
        /* Z1 = Hbar @ Wcat[:, 0:512]^T ; Z2 = Hbar @ Wcat[:, 512:1024]^T */
        gemm3<<<dim3(KX / GBN, N_OBJ / GBM), 256, GEMM_SMEM>>>(
            pHbh, pHbl, HDIM, pWch, pWcl, KX, pZ1, KX, HDIM, HDIM);
        gemm3<<<dim3(KX / GBN, N_OBJ / GBM), 256, GEMM_SMEM>>>(
            pHbh, pHbl, HDIM, pWch + 512, pWcl + 512, KX, pZ2, KX, HDIM, HDIM);
        if (t > 0) {
            prop_kernel<<<dim3(HDIM / P_HT, (C_CLS + P_DT - 1) / P_DT, N_OBJ),
                          256>>>(matrix);
            /* Yres[:, 0:1024] = X @ Wcat[0:1024]^T : hi-only lean, K=1536 */
            gemm1<<<dim3(1024 / GBN, NCROW / GBM), 256, GEMM1_SMEM>>>(
                pXh, KX, pWch, KX, pY, KX, KX);
            /* Yres[:, 1024:1536]: Wcat rows 1024.. zero for k>=1024 -> K=1024 */
            gemm1<<<dim3(512 / GBN, NCROW / GBM), 256, GEMM1_SMEM>>>(
                pXh, KX, pWch + (size_t)1024 * KX, KX, pY + 1024, KX, 1024);
        }
        pw_rv<<<PW_BLOCKS, 256>>>(b4w, b4u, t == 0 ? 1 : 0);
        /* U5 = (rv*h) @ W5u^T : hi-only lean */
        gemm1<<<dim3(HDIM / GBN, NCROW / GBM), 256, GEMM1_SMEM>>>(
            pRHh, HDIM, pW5uh, HDIM, pU5, HDIM, HDIM);
        pw_update<<<PW_BLOCKS, 256>>>(b3w, b3u, b5w, b5u, t == 0 ? 1 : 0);
    }

    /* O1 = hidden @ Wo1^T — full corrections (classifier-facing) */
    gemm3<<<dim3(HDIM / GBN, NCROW / GBM), 256, GEMM_SMEM>>>(
        pHh, pHl, HDIM, pWoh, pWol, 2 * HDIM, pO1, HDIM, HDIM, HDIM);
    pw_relu<<<PW_BLOCKS, 256>>>(bout);

    cls_partial<<<dim3(N_OBJ / 32, C_CLS), 160>>>(wcls);
    cls_reduce<<<(N_OBJ * C_CLS + 255) / 256, 256>>>(bcls, out);
}

// round 17
// speedup vs baseline: 2.1748x; 1.1255x over previous
#include <cuda_runtime.h>
#include <cuda_fp16.h>
#include <math.h>

#define N_OBJ 256
#define C_CLS 151
#define HDIM  512
#define NCROW (N_OBJ * C_CLS)
#define KX    1536
#define CH    (C_CLS * HDIM)
#define DPAD  256
#define CPAD  160               /* c padded for MMA K */
#define DROWS 192               /* d padded for M tiles */

#define LO_SCALE     256.0f
#define LO_INV_SCALE 0.00390625f

/* ------------------- scratch: device globals (no allocs) ------------------ */
__device__ float g_hidden[(size_t)NCROW * HDIM];
__device__ half  g_Xh[(size_t)NCROW * KX];
__device__ float g_Y[(size_t)NCROW * KX];
__device__ float g_Y0[(size_t)N_OBJ * 1024];
__device__ float g_YS[(size_t)DPAD * KX];
__device__ float g_Z1[(size_t)N_OBJ * KX];
__device__ float g_Z2[(size_t)N_OBJ * KX];
__device__ float g_Hbar[N_OBJ * HDIM];
__device__ half  g_Hbh[N_OBJ * HDIM];
__device__ half  g_Hbl[N_OBJ * HDIM];
__device__ half  g_MSh[(size_t)DPAD * 1024];
__device__ half  g_MSl[(size_t)DPAD * 1024];
__device__ float g_cM1[C_CLS];
__device__ float g_cM2[C_CLS];
__device__ half  g_M1t[DROWS * CPAD];
__device__ half  g_M2t[DROWS * CPAD];
__device__ half  g_Hdt[(size_t)N_OBJ * HDIM * CPAD];
__device__ half  g_RHh[(size_t)NCROW * HDIM];
__device__ half  g_Hh[(size_t)NCROW * HDIM];
__device__ half  g_Hl[(size_t)NCROW * HDIM];
__device__ float g_U5[(size_t)NCROW * HDIM];
__device__ float g_O1[(size_t)NCROW * HDIM];
__device__ float g_S[CH];
__device__ float g_MS1[CH];
__device__ float g_MS2[CH];
__device__ half  g_Wch[(size_t)KX * KX];
__device__ half  g_Wcl[(size_t)KX * KX];
__device__ half  g_W5uh[HDIM * HDIM];
__device__ half  g_Woh[HDIM * 2 * HDIM];
__device__ half  g_Wol[HDIM * 2 * HDIM];
__device__ half  g_Ih[N_OBJ * HDIM];
__device__ half  g_Il[N_OBJ * HDIM];
__device__ float g_B2[N_OBJ * HDIM];
__device__ float g_Pcls[(size_t)C_CLS * N_OBJ * C_CLS];

/* ------------------------------ helpers ----------------------------------- */
__device__ __forceinline__ void split_store(float v, half* ph, half* pl)
{
    half hi = __float2half_rn(v);
    *ph = hi;
    *pl = __float2half_rn((v - __half2float(hi)) * LO_SCALE);
}

__device__ __forceinline__ unsigned smem_u32(const void* p)
{
    return (unsigned)__cvta_generic_to_shared(p);
}

__device__ __forceinline__ void ldsm4(unsigned* r, unsigned addr)
{
    asm volatile("ldmatrix.sync.aligned.m8n8.x4.shared.b16 {%0,%1,%2,%3},[%4];"
        : "=r"(r[0]), "=r"(r[1]), "=r"(r[2]), "=r"(r[3]) : "r"(addr));
}

__device__ __forceinline__ void mma16816(float* c, const unsigned* a, const unsigned* b)
{
    asm volatile("mma.sync.aligned.m16n8k16.row.col.f32.f16.f16.f32 "
        "{%0,%1,%2,%3},{%4,%5,%6,%7},{%8,%9},{%0,%1,%2,%3};"
        : "+f"(c[0]), "+f"(c[1]), "+f"(c[2]), "+f"(c[3])
        : "r"(a[0]), "r"(a[1]), "r"(a[2]), "r"(a[3]), "r"(b[0]), "r"(b[1]));
}

__device__ __forceinline__ void cp16(void* dst_smem, const void* src_gmem)
{
    unsigned s = smem_u32(dst_smem);
    asm volatile("cp.async.cg.shared.global [%0], [%1], 16;" :: "r"(s), "l"(src_gmem));
}

__device__ __forceinline__ void cp_commit()
{
    asm volatile("cp.async.commit_group;" ::: "memory");
}

__device__ __forceinline__ void cp_wait0()
{
    asm volatile("cp.async.wait_group 0;" ::: "memory");
}

/* ------------------------- weight concat + split --------------------------- */
__global__ void build_wcat(const float* __restrict__ w3w, const float* __restrict__ w3u,
                           const float* __restrict__ w4w, const float* __restrict__ w4u,
                           const float* __restrict__ w5w)
{
    int idx = blockIdx.x * blockDim.x + threadIdx.x;
    if (idx >= KX * KX) return;
    int o = idx / KX;
    int k = idx - o * KX;
    float v;
    if (o < 512) {
        v = (k < 1024) ? w3w[o * 1024 + k] : w3u[o * 512 + (k - 1024)];
    } else if (o < 1024) {
        int oo = o - 512;
        v = (k < 1024) ? w4w[oo * 1024 + k] : w4u[oo * 512 + (k - 1024)];
    } else {
        int oo = o - 1024;
        v = (k < 1024) ? w5w[oo * 1024 + k] : 0.0f;
    }
    split_store(v, &g_Wch[idx], &g_Wcl[idx]);
}

__global__ void split_f32(const float* __restrict__ src, half* __restrict__ dh,
                          half* __restrict__ dl, int n)
{
    int idx = blockIdx.x * blockDim.x + threadIdx.x;
    if (idx >= n) return;
    split_store(src[idx], &dh[idx], &dl[idx]);
}

__global__ void conv_f16(const float* __restrict__ src, half* __restrict__ dh, int n)
{
    int idx = blockIdx.x * blockDim.x + threadIdx.x;
    if (idx >= n) return;
    dh[idx] = __float2half_rn(src[idx]);
}

/* --------- M transposes (padded, fp16): M1t = M^T, M2t = M ---------------- */
__global__ void mt_build(const float* __restrict__ M)
{
    int idx = blockIdx.x * blockDim.x + threadIdx.x;
    if (idx >= DROWS * CPAD) return;
    int d = idx / CPAD;
    int c = idx - d * CPAD;
    bool ok = (d < C_CLS) && (c < C_CLS);
    g_M1t[idx] = __float2half_rn(ok ? M[c * C_CLS + d] : 0.f);
    g_M2t[idx] = __float2half_rn(ok ? M[d * C_CLS + c] : 0.f);
}

/* ------------------- init hidden[n][c][h] = input[n][h] ------------------- */
__global__ void init_hidden(const float* __restrict__ input)
{
    size_t idx = (size_t)blockIdx.x * blockDim.x + threadIdx.x;
    int h = (int)(idx & (HDIM - 1));
    size_t m = idx >> 9;
    int n = (int)(m / C_CLS);
    g_hidden[idx] = input[(size_t)n * HDIM + h];
}

/* -------------------- S[c][h] = sum_n hidden[n][c][h] --------------------- */
__global__ void colsum_kernel()
{
    int idx = blockIdx.x * blockDim.x + threadIdx.x;
    float s = 0.f;
    #pragma unroll 4
    for (int n = 0; n < N_OBJ; n++) s += g_hidden[(size_t)n * CH + idx];
    g_S[idx] = s;
}

/* ------------- Hbar[n][h] = mean_c hidden[n][c][h]  (+ hi/lo split) ------- */
__global__ void hbar_kernel()
{
    int idx = blockIdx.x * blockDim.x + threadIdx.x;
    int n = idx >> 9;
    int h = idx & (HDIM - 1);
    const float* p = g_hidden + (size_t)n * CH + h;
    float s = 0.f;
    for (int c = 0; c < C_CLS; c++) s += p[(size_t)c * HDIM];
    float hb = s * (1.0f / C_CLS);
    g_Hbar[idx] = hb;
    split_store(hb, &g_Hbh[idx], &g_Hbl[idx]);
}

/* ------------- cM1[d] = sum_c M[c][d] ; cM2[d] = sum_c M[d][c] ------------ */
__global__ void cm_kernel(const float* __restrict__ M)
{
    int d = blockIdx.x * blockDim.x + threadIdx.x;
    if (d >= C_CLS) return;
    float s1 = 0.f, s2 = 0.f;
    for (int c = 0; c < C_CLS; c++) {
        s1 += M[c * C_CLS + d];
        s2 += M[d * C_CLS + c];
    }
    g_cM1[d] = s1;
    g_cM2[d] = s2;
}

/* --------- MS1[d][h]=sum_c M[c][d]S[c][h] ; MS2[d][h]=sum_c M[d][c]S ------ */
__global__ void msprop_kernel(const float* __restrict__ M)
{
    int idx = blockIdx.x * blockDim.x + threadIdx.x;
    int d = idx / HDIM;
    int h = idx - d * HDIM;
    float s1 = 0.f, s2 = 0.f;
    for (int c = 0; c < C_CLS; c++) {
        float sv = g_S[c * HDIM + h];
        s1 += M[c * C_CLS + d] * sv;
        s2 += M[d * C_CLS + c] * sv;
    }
    g_MS1[idx] = s1;
    g_MS2[idx] = s2;
}

/* --- MScat padded split: MSh/MSl[d][k], d<DPAD, k<1024 --------------------- */
__global__ void ms_split_kernel()
{
    int idx = blockIdx.x * blockDim.x + threadIdx.x;
    int d = idx >> 10;
    int k = idx & 1023;
    float v = 0.f;
    if (d < C_CLS)
        v = (k < 512) ? g_MS1[d * HDIM + k] : g_MS2[d * HDIM + (k - 512)];
    split_store(v, &g_MSh[idx], &g_MSl[idx]);
}

/* --- Hdt[n][h][c] = hidden[n][c][h] - Hbar[n][h]  (fp16, c zero-padded) --- */
#define HT_HB 64
__global__ __launch_bounds__(256) void hdt_kernel()
{
    __shared__ half s[HT_HB][CPAD + 8];
    int h0 = blockIdx.x * HT_HB;
    int n  = blockIdx.y;
    int tid = threadIdx.x;
    /* zero pad columns */
    for (int i = tid; i < HT_HB * (CPAD + 8); i += 256)
        ((half*)s)[i] = __float2half_rn(0.f);
    __syncthreads();
    const float* Hn = g_hidden + (size_t)n * CH;
    const float* Hb = g_Hbar + (size_t)n * HDIM + h0;
    for (int i = tid; i < C_CLS * HT_HB; i += 256) {
        int c = i / HT_HB;
        int hh = i - c * HT_HB;
        float v = Hn[(size_t)c * HDIM + h0 + hh] - Hb[hh];
        s[hh][c] = __float2half_rn(v);
    }
    __syncthreads();
    half* dst = g_Hdt + ((size_t)n * HDIM + h0) * CPAD;
    for (int i = tid; i < HT_HB * CPAD; i += 256) {
        int hh = i / CPAD;
        int c  = i - hh * CPAD;
        dst[(size_t)hh * CPAD + c] = s[hh][c];
    }
}

/* --- prop via MMA: Xh[(n,d), 0:512] = -M1t@Hdt^T ; [512:1024] = -M2t@... -- */
#define PM_D 64
#define PM_H 128
#define PM_SROW (CPAD + 8)
__global__ __launch_bounds__(128) void prop_mma()
{
    extern __shared__ half sm[];
    half* sA1 = sm;                       /* [PM_D][PM_SROW] */
    half* sA2 = sm + PM_D * PM_SROW;
    half* sB  = sm + 2 * PM_D * PM_SROW;  /* [PM_H][PM_SROW] */

    int tid = threadIdx.x;
    int warp = tid >> 5;
    int lane = tid & 31;
    int h0 = blockIdx.x * PM_H;
    int d0 = blockIdx.y * PM_D;
    int n  = blockIdx.z;

    for (int i = tid; i < PM_D * (CPAD / 8); i += 128) {
        int r = i / (CPAD / 8);
        int ck = (i - r * (CPAD / 8)) * 8;
        cp16(&sA1[r * PM_SROW + ck], g_M1t + (d0 + r) * CPAD + ck);
        cp16(&sA2[r * PM_SROW + ck], g_M2t + (d0 + r) * CPAD + ck);
    }
    const half* Bsrc = g_Hdt + ((size_t)n * HDIM + h0) * CPAD;
    for (int i = tid; i < PM_H * (CPAD / 8); i += 128) {
        int r = i / (CPAD / 8);
        int ck = (i - r * (CPAD / 8)) * 8;
        cp16(&sB[r * PM_SROW + ck], Bsrc + (size_t)r * CPAD + ck);
    }
    cp_commit();
    cp_wait0();
    __syncthreads();

    float a1[4][4][4];
    float a2[4][4][4];
    #pragma unroll
    for (int i = 0; i < 4; i++) {
        #pragma unroll
        for (int j = 0; j < 4; j++) {
            #pragma unroll
            for (int q = 0; q < 4; q++) {
                a1[i][j][q] = 0.f;
                a2[i][j][q] = 0.f;
            }
        }
    }

    for (int k0 = 0; k0 < CPAD; k0 += 16) {
        unsigned bf[2][4];
        #pragma unroll
        for (int p = 0; p < 2; p++) {
            int nn = warp * 32 + p * 16 + ((lane >> 4) << 3) + (lane & 7);
            int kb = k0 + (((lane >> 3) & 1) << 3);
            ldsm4(bf[p], smem_u32(&sB[nn * PM_SROW + kb]));
        }
        #pragma unroll
        for (int mf = 0; mf < 4; mf++) {
            int mm = mf * 16 + (lane & 15);
            int ka = k0 + ((lane >> 4) << 3);
            unsigned af1[4];
            unsigned af2[4];
            ldsm4(af1, smem_u32(&sA1[mm * PM_SROW + ka]));
            ldsm4(af2, smem_u32(&sA2[mm * PM_SROW + ka]));
            #pragma unroll
            for (int nf = 0; nf < 4; nf++)
                mma16816(a1[mf][nf], af1, &bf[nf >> 1][(nf & 1) * 2]);
            #pragma unroll
            for (int nf = 0; nf < 4; nf++)
                mma16816(a2[mf][nf], af2, &bf[nf >> 1][(nf & 1) * 2]);
        }
    }

    int r = lane >> 2;
    int cb = (lane & 3) * 2;
    #pragma unroll
    for (int mf = 0; mf < 4; mf++) {
        #pragma unroll
        for (int nf = 0; nf < 4; nf++) {
            int hcol = h0 + warp * 32 + nf * 8 + cb;
            int da = d0 + mf * 16 + r;
            if (da < C_CLS) {
                size_t mrow = ((size_t)n * C_CLS + da) * KX;
                g_Xh[mrow + hcol]           = __float2half_rn(-a1[mf][nf][0]);
                g_Xh[mrow + hcol + 1]       = __float2half_rn(-a1[mf][nf][1]);
                g_Xh[mrow + 512 + hcol]     = __float2half_rn(-a2[mf][nf][0]);
                g_Xh[mrow + 512 + hcol + 1] = __float2half_rn(-a2[mf][nf][1]);
            }
            int db = da + 8;
            if (db < C_CLS) {
                size_t mrow = ((size_t)n * C_CLS + db) * KX;
                g_Xh[mrow + hcol]           = __float2half_rn(-a1[mf][nf][2]);
                g_Xh[mrow + hcol + 1]       = __float2half_rn(-a1[mf][nf][3]);
                g_Xh[mrow + 512 + hcol]     = __float2half_rn(-a2[mf][nf][2]);
                g_Xh[mrow + 512 + hcol + 1] = __float2half_rn(-a2[mf][nf][3]);
            }
        }
    }
}

/* --------- full-precision tensor GEMM (3-product split + drain) ------------ */
#define GBM 128
#define GBN 128
#define GBK 32
#define SROW 40
#define SA_IDX(b, hl, r, c) (((((b) * 2 + (hl)) * GBM) + (r)) * SROW + (c))
#define SB_IDX(b, hl, r, c) (((((b) * 2 + (hl)) * GBN) + (r)) * SROW + (c))

__device__ __forceinline__ void gemm_load_stage(
    half* sA, half* sB, int s, int k0, int tid, int m0, int n0,
    const half* Ah, const half* Al, int lda,
    const half* Bh, const half* Bl, int ldb, bool corr)
{
    #pragma unroll
    for (int t = 0; t < 2; t++) {
        int idx = tid + t * 256;
        int row = idx >> 2;
        int ck  = (idx & 3) * 8;
        cp16(&sA[SA_IDX(s, 0, row, ck)], Ah + (size_t)(m0 + row) * lda + k0 + ck);
        cp16(&sB[SB_IDX(s, 0, row, ck)], Bh + (size_t)(n0 + row) * ldb + k0 + ck);
        if (corr) {
            cp16(&sA[SA_IDX(s, 1, row, ck)], Al + (size_t)(m0 + row) * lda + k0 + ck);
            cp16(&sB[SB_IDX(s, 1, row, ck)], Bl + (size_t)(n0 + row) * ldb + k0 + ck);
        }
    }
}

__global__ __launch_bounds__(256, 1) void gemm3(
    const half* __restrict__ Ah, const half* __restrict__ Al, int lda,
    const half* __restrict__ Bh, const half* __restrict__ Bl, int ldb,
    float* __restrict__ Cout, int ldc, int K, int KC)
{
    extern __shared__ half smem[];
    half* sA = smem;
    half* sB = smem + 2 * 2 * GBM * SROW;

    int tid = threadIdx.x;
    int warp = tid >> 5;
    int lane = tid & 31;
    int wm = warp >> 2;
    int wn = warp & 3;
    int m0 = blockIdx.y * GBM;
    int n0 = blockIdx.x * GBN;

    float acc[4][4][4];
    float accS[4][4][4];
    float acl[4][4][4];
    #pragma unroll
    for (int i = 0; i < 4; i++) {
        #pragma unroll
        for (int j = 0; j < 4; j++) {
            #pragma unroll
            for (int q = 0; q < 4; q++) {
                acc[i][j][q]  = 0.f;
                accS[i][j][q] = 0.f;
                acl[i][j][q]  = 0.f;
            }
        }
    }

    gemm_load_stage(sA, sB, 0, 0, tid, m0, n0, Ah, Al, lda, Bh, Bl, ldb, 0 < KC);
    cp_commit();

    int nit = K / GBK;
    for (int it = 0; it < nit; it++) {
        int cur = it & 1;
        bool corr = (it * GBK) < KC;
        cp_wait0();
        __syncthreads();
        if (it + 1 < nit) {
            gemm_load_stage(sA, sB, cur ^ 1, (it + 1) * GBK, tid, m0, n0,
                            Ah, Al, lda, Bh, Bl, ldb, ((it + 1) * GBK) < KC);
            cp_commit();
        }
        #pragma unroll
        for (int ks = 0; ks < 2; ks++) {
            int kk = ks * 16;
            unsigned bhf[2][4];
            unsigned blf[2][4];
            #pragma unroll
            for (int p = 0; p < 2; p++) {
                int nn = wn * 32 + p * 16 + ((lane >> 4) << 3) + (lane & 7);
                int kb = kk + (((lane >> 3) & 1) << 3);
                ldsm4(bhf[p], smem_u32(&sB[SB_IDX(cur, 0, nn, kb)]));
                if (corr)
                    ldsm4(blf[p], smem_u32(&sB[SB_IDX(cur, 1, nn, kb)]));
            }
            #pragma unroll
            for (int mf = 0; mf < 4; mf++) {
                int mm = wm * 64 + mf * 16 + (lane & 15);
                int ka = kk + ((lane >> 4) << 3);
                unsigned ahf[4];
                unsigned alf[4];
                ldsm4(ahf, smem_u32(&sA[SA_IDX(cur, 0, mm, ka)]));
                if (corr)
                    ldsm4(alf, smem_u32(&sA[SA_IDX(cur, 1, mm, ka)]));
                #pragma unroll
                for (int nf = 0; nf < 4; nf++)
                    mma16816(acc[mf][nf], ahf, &bhf[nf >> 1][(nf & 1) * 2]);
                if (corr) {
                    #pragma unroll
                    for (int nf = 0; nf < 4; nf++)
                        mma16816(acl[mf][nf], ahf, &blf[nf >> 1][(nf & 1) * 2]);
                    #pragma unroll
                    for (int nf = 0; nf < 4; nf++)
                        mma16816(acl[mf][nf], alf, &bhf[nf >> 1][(nf & 1) * 2]);
                }
            }
        }
        #pragma unroll
        for (int mf = 0; mf < 4; mf++) {
            #pragma unroll
            for (int nf = 0; nf < 4; nf++) {
                #pragma unroll
                for (int q = 0; q < 4; q++) {
                    accS[mf][nf][q] += acc[mf][nf][q];
                    acc[mf][nf][q] = 0.f;
                }
            }
        }
        __syncthreads();
    }

    int r = lane >> 2;
    int cb = (lane & 3) * 2;
    #pragma unroll
    for (int mf = 0; mf < 4; mf++) {
        #pragma unroll
        for (int nf = 0; nf < 4; nf++) {
            float* Cp = Cout + (size_t)(m0 + wm * 64 + mf * 16 + r) * ldc
                             + (n0 + wn * 32 + nf * 8 + cb);
            Cp[0] = accS[mf][nf][0] + acl[mf][nf][0] * LO_INV_SCALE;
            Cp[1] = accS[mf][nf][1] + acl[mf][nf][1] * LO_INV_SCALE;
            Cp += (size_t)8 * ldc;
            Cp[0] = accS[mf][nf][2] + acl[mf][nf][2] * LO_INV_SCALE;
            Cp[1] = accS[mf][nf][3] + acl[mf][nf][3] * LO_INV_SCALE;
        }
    }
}

/* --------- lean hi-only tensor GEMM: 2 CTAs/SM, no drain -------------------- */
#define S1A_IDX(b, r, c) ((((b) * GBM) + (r)) * SROW + (c))
#define S1B_IDX(b, r, c) ((((b) * GBN) + (r)) * SROW + (c))

__device__ __forceinline__ void gemm1_load_stage(
    half* sA, half* sB, int s, int k0, int tid, int m0, int n0,
    const half* Ah, int lda, const half* Bh, int ldb)
{
    #pragma unroll
    for (int t = 0; t < 2; t++) {
        int idx = tid + t * 256;
        int row = idx >> 2;
        int ck  = (idx & 3) * 8;
        cp16(&sA[S1A_IDX(s, row, ck)], Ah + (size_t)(m0 + row) * lda + k0 + ck);
        cp16(&sB[S1B_IDX(s, row, ck)], Bh + (size_t)(n0 + row) * ldb + k0 + ck);
    }
}

__global__ __launch_bounds__(256, 2) void gemm1(
    const half* __restrict__ Ah, int lda,
    const half* __restrict__ Bh, int ldb,
    float* __restrict__ Cout, int ldc, int K)
{
    extern __shared__ half smem[];
    half* sA = smem;
    half* sB = smem + 2 * GBM * SROW;

    int tid = threadIdx.x;
    int warp = tid >> 5;
    int lane = tid & 31;
    int wm = warp >> 2;
    int wn = warp & 3;
    int m0 = blockIdx.y * GBM;
    int n0 = blockIdx.x * GBN;

    float acc[4][4][4];
    #pragma unroll
    for (int i = 0; i < 4; i++) {
        #pragma unroll
        for (int j = 0; j < 4; j++) {
            acc[i][j][0] = 0.f;
            acc[i][j][1] = 0.f;
            acc[i][j][2] = 0.f;
            acc[i][j][3] = 0.f;
        }
    }

    gemm1_load_stage(sA, sB, 0, 0, tid, m0, n0, Ah, lda, Bh, ldb);
    cp_commit();

    int nit = K / GBK;
    for (int it = 0; it < nit; it++) {
        int cur = it & 1;
        cp_wait0();
        __syncthreads();
        if (it + 1 < nit) {
            gemm1_load_stage(sA, sB, cur ^ 1, (it + 1) * GBK, tid, m0, n0,
                             Ah, lda, Bh, ldb);
            cp_commit();
        }
        #pragma unroll
        for (int ks = 0; ks < 2; ks++) {
            int kk = ks * 16;
            unsigned bhf[2][4];
            #pragma unroll
            for (int p = 0; p < 2; p++) {
                int nn = wn * 32 + p * 16 + ((lane >> 4) << 3) + (lane & 7);
                int kb = kk + (((lane >> 3) & 1) << 3);
                ldsm4(bhf[p], smem_u32(&sB[S1B_IDX(cur, nn, kb)]));
            }
            #pragma unroll
            for (int mf = 0; mf < 4; mf++) {
                int mm = wm * 64 + mf * 16 + (lane & 15);
                int ka = kk + ((lane >> 4) << 3);
                unsigned ahf[4];
                ldsm4(ahf, smem_u32(&sA[S1A_IDX(cur, mm, ka)]));
                #pragma unroll
                for (int nf = 0; nf < 4; nf++)
                    mma16816(acc[mf][nf], ahf, &bhf[nf >> 1][(nf & 1) * 2]);
            }
        }
        __syncthreads();
    }

    int r = lane >> 2;
    int cb = (lane & 3) * 2;
    #pragma unroll
    for (int mf = 0; mf < 4; mf++) {
        #pragma unroll
        for (int nf = 0; nf < 4; nf++) {
            float* Cp = Cout + (size_t)(m0 + wm * 64 + mf * 16 + r) * ldc
                             + (n0 + wn * 32 + nf * 8 + cb);
            Cp[0] = acc[mf][nf][0];
            Cp[1] = acc[mf][nf][1];
            Cp += (size_t)8 * ldc;
            Cp[0] = acc[mf][nf][2];
            Cp[1] = acc[mf][nf][3];
        }
    }
}

/* ------------------------------ pointwise --------------------------------- */
__device__ __forceinline__ float sigmoidf_(float x)
{
    return 1.f / (1.f + expf(-x));
}

__global__ void pw_rv(const float* __restrict__ b4w, const float* __restrict__ b4u,
                      int t0)
{
    size_t idx = (size_t)blockIdx.x * blockDim.x + threadIdx.x;
    int h = (int)(idx & (HDIM - 1));
    size_t m = idx >> 9;
    int n = (int)(m / C_CLS);
    int d = (int)(m - (size_t)n * C_CLS);
    size_t o = 512 + h;
    float yv = t0 ? g_Y0[(size_t)n * 1024 + o] : g_Y[m * KX + o];
    float pre = yv + g_YS[(size_t)d * KX + o]
              - g_cM1[d] * g_Z1[(size_t)n * KX + o]
              - g_cM2[d] * g_Z2[(size_t)n * KX + o]
              + b4w[h] + b4u[h];
    float rh = sigmoidf_(pre) * g_hidden[idx];
    g_RHh[idx] = __float2half_rn(rh);
}

__global__ void pw_update(const float* __restrict__ b3w, const float* __restrict__ b3u,
                          const float* __restrict__ b5w, const float* __restrict__ b5u,
                          int t0)
{
    size_t idx = (size_t)blockIdx.x * blockDim.x + threadIdx.x;
    int h = (int)(idx & (HDIM - 1));
    size_t m = idx >> 9;
    int n = (int)(m / C_CLS);
    int d = (int)(m - (size_t)n * C_CLS);
    const float* ys = g_YS + (size_t)d * KX;
    const float* z1 = g_Z1 + (size_t)n * KX;
    const float* z2 = g_Z2 + (size_t)n * KX;
    float c1 = g_cM1[d];
    float c2 = g_cM2[d];
    float y1 = t0 ? g_Y0[(size_t)n * 1024 + h] : g_Y[m * KX + h];
    float y3 = t0 ? 0.f : g_Y[m * KX + 1024 + h];
    float preZ = y1 + ys[h] - c1 * z1[h] - c2 * z2[h] + b3w[h] + b3u[h];
    float preH = y3 + ys[1024 + h] - c1 * z1[1024 + h] - c2 * z2[1024 + h]
               + b5w[h] + g_U5[idx] + b5u[h];
    float z  = sigmoidf_(preZ);
    float hv = tanhf(preH);
    float hp = g_hidden[idx];
    float nh = (1.f - z) * hp + z * hv;
    g_hidden[idx] = nh;
    split_store(nh, &g_Hh[idx], &g_Hl[idx]);
    /* X segment 3 for the NEXT step (= new hidden, hi only) */
    g_Xh[m * KX + 1024 + h] = g_Hh[idx];
}

__global__ void pw_relu(const float* __restrict__ bout)
{
    size_t idx = (size_t)blockIdx.x * blockDim.x + threadIdx.x;
    int h = (int)(idx & (HDIM - 1));
    size_t m = idx >> 9;
    int n = (int)(m / C_CLS);
    float v = g_O1[idx] + g_B2[n * HDIM + h] + bout[h];
    g_O1[idx] = v > 0.f ? v : 0.f;
}

/* --------------------- classifier: split-K over c ------------------------- */
__global__ __launch_bounds__(160) void cls_partial(const float* __restrict__ wcls)
{
    __shared__ float O1s[32][64];
    int nt = blockIdx.x;
    int ks = blockIdx.y;
    int j = threadIdx.x;
    float acc[32];
    #pragma unroll
    for (int nn = 0; nn < 32; nn++) acc[nn] = 0.f;

    for (int kb = 0; kb < 512; kb += 64) {
        for (int f = threadIdx.x; f < 32 * 64; f += 160) {
            int nn = f >> 6;
            int kk = f & 63;
            O1s[nn][kk] = g_O1[(size_t)(nt * 32 + nn) * CH + ks * 512 + kb + kk];
        }
        __syncthreads();
        if (j < C_CLS) {
            const float* wrow = wcls + (size_t)j * CH + ks * 512 + kb;
            #pragma unroll 4
            for (int kk = 0; kk < 64; kk += 4) {
                float4 w = *(const float4*)(wrow + kk);
                #pragma unroll
                for (int nn = 0; nn < 32; nn++) {
                    float4 o = *(const float4*)&O1s[nn][kk];
                    acc[nn] += w.x * o.x + w.y * o.y + w.z * o.z + w.w * o.w;
                }
            }
        }
        __syncthreads();
    }
    if (j < C_CLS) {
        #pragma unroll
        for (int nn = 0; nn < 32; nn++)
            g_Pcls[((size_t)ks * N_OBJ + nt * 32 + nn) * C_CLS + j] = acc[nn];
    }
}

__global__ void cls_reduce(const float* __restrict__ bcls, float* __restrict__ out)
{
    int idx = blockIdx.x * blockDim.x + threadIdx.x;
    if (idx >= N_OBJ * C_CLS) return;
    int n = idx / C_CLS;
    int j = idx - n * C_CLS;
    float s = bcls[j];
    for (int ks = 0; ks < C_CLS; ks++)
        s += g_Pcls[((size_t)ks * N_OBJ + n) * C_CLS + j];
    out[idx] = s;
}

/* --------------------------------------------------------------------------- */
extern "C" void kernel_launch(void* const* d_in, const int* in_sizes, int n_in,
                              void* d_out, int out_size)
{
    const float* input  = (const float*)d_in[0];
    const float* matrix = (const float*)d_in[1];
    const float* w3w = (const float*)d_in[2];
    const float* b3w = (const float*)d_in[3];
    const float* w3u = (const float*)d_in[4];
    const float* b3u = (const float*)d_in[5];
    const float* w4w = (const float*)d_in[6];
    const float* b4w = (const float*)d_in[7];
    const float* w4u = (const float*)d_in[8];
    const float* b4u = (const float*)d_in[9];
    const float* w5w = (const float*)d_in[10];
    const float* b5w = (const float*)d_in[11];
    const float* w5u = (const float*)d_in[12];
    const float* b5u = (const float*)d_in[13];
    const float* wout = (const float*)d_in[14];
    const float* bout = (const float*)d_in[15];
    const float* wcls = (const float*)d_in[16];
    const float* bcls = (const float*)d_in[17];
    float* out = (float*)d_out;

    void* tmp = 0;
    float* pY;
    float* pY0;
    float* pYS;
    float* pZ1;
    float* pZ2;
    float* pU5;
    float* pO1;
    float* pB2;
    half* pXh;
    half* pWch;
    half* pWcl;
    half* pRHh;
    half* pHh;
    half* pHl;
    half* pW5uh;
    half* pWoh;
    half* pWol;
    half* pIh;
    half* pIl;
    half* pMSh;
    half* pMSl;
    half* pHbh;
    half* pHbl;

    cudaGetSymbolAddress(&tmp, g_Y);     pY    = (float*)tmp;
    cudaGetSymbolAddress(&tmp, g_Y0);    pY0   = (float*)tmp;
    cudaGetSymbolAddress(&tmp, g_YS);    pYS   = (float*)tmp;
    cudaGetSymbolAddress(&tmp, g_Z1);    pZ1   = (float*)tmp;
    cudaGetSymbolAddress(&tmp, g_Z2);    pZ2   = (float*)tmp;
    cudaGetSymbolAddress(&tmp, g_U5);    pU5   = (float*)tmp;
    cudaGetSymbolAddress(&tmp, g_O1);    pO1   = (float*)tmp;
    cudaGetSymbolAddress(&tmp, g_B2);    pB2   = (float*)tmp;
    cudaGetSymbolAddress(&tmp, g_Xh);    pXh   = (half*)tmp;
    cudaGetSymbolAddress(&tmp, g_Wch);   pWch  = (half*)tmp;
    cudaGetSymbolAddress(&tmp, g_Wcl);   pWcl  = (half*)tmp;
    cudaGetSymbolAddress(&tmp, g_RHh);   pRHh  = (half*)tmp;
    cudaGetSymbolAddress(&tmp, g_Hh);    pHh   = (half*)tmp;
    cudaGetSymbolAddress(&tmp, g_Hl);    pHl   = (half*)tmp;
    cudaGetSymbolAddress(&tmp, g_W5uh);  pW5uh = (half*)tmp;
    cudaGetSymbolAddress(&tmp, g_Woh);   pWoh  = (half*)tmp;
    cudaGetSymbolAddress(&tmp, g_Wol);   pWol  = (half*)tmp;
    cudaGetSymbolAddress(&tmp, g_Ih);    pIh   = (half*)tmp;
    cudaGetSymbolAddress(&tmp, g_Il);    pIl   = (half*)tmp;
    cudaGetSymbolAddress(&tmp, g_MSh);   pMSh  = (half*)tmp;
    cudaGetSymbolAddress(&tmp, g_MSl);   pMSl  = (half*)tmp;
    cudaGetSymbolAddress(&tmp, g_Hbh);   pHbh  = (half*)tmp;
    cudaGetSymbolAddress(&tmp, g_Hbl);   pHbl  = (half*)tmp;

    const int GEMM_SMEM  = 2 * 2 * (GBM + GBN) * SROW * (int)sizeof(half);
    const int GEMM1_SMEM = 2 * (GBM + GBN) * SROW * (int)sizeof(half);
    const int PM_SMEM    = (2 * PM_D + PM_H) * PM_SROW * (int)sizeof(half);
    cudaFuncSetAttribute(gemm3, cudaFuncAttributeMaxDynamicSharedMemorySize, GEMM_SMEM);
    cudaFuncSetAttribute(gemm1, cudaFuncAttributeMaxDynamicSharedMemorySize, GEMM1_SMEM);
    cudaFuncSetAttribute(prop_mma, cudaFuncAttributeMaxDynamicSharedMemorySize, PM_SMEM);

    const int PW_BLOCKS = (int)(((size_t)NCROW * HDIM) / 256);
    const int CH_BLOCKS = CH / 256;
    const int NH_BLOCKS = (N_OBJ * HDIM) / 256;

    build_wcat<<<(KX * KX + 255) / 256, 256>>>(w3w, w3u, w4w, w4u, w5w);
    split_f32<<<(HDIM * 2 * HDIM + 255) / 256, 256>>>(wout, pWoh, pWol,
                                                      HDIM * 2 * HDIM);
    split_f32<<<(N_OBJ * HDIM + 255) / 256, 256>>>(input, pIh, pIl,
                                                   N_OBJ * HDIM);
    /* B2 = input @ Wo2^T — full corrections (launch #3, profiled) */
    gemm3<<<dim3(HDIM / GBN, N_OBJ / GBM), 256, GEMM_SMEM>>>(
        pIh, pIl, HDIM, pWoh + 512, pWol + 512, 2 * HDIM, pB2, HDIM, HDIM, HDIM);
    conv_f16<<<(HDIM * HDIM + 255) / 256, 256>>>(w5u, pW5uh, HDIM * HDIM);
    cm_kernel<<<1, 256>>>(matrix);
    mt_build<<<(DROWS * CPAD + 255) / 256, 256>>>(matrix);
    init_hidden<<<PW_BLOCKS, 256>>>(input);

    /* t=0 Y shortcut: Y0[n, 0:1024] = input @ W34u^T (Wcat cols 1024:1536) */
    gemm3<<<dim3(1024 / GBN, N_OBJ / GBM), 256, GEMM_SMEM>>>(
        pIh, pIl, HDIM, pWch + 1024, pWcl + 1024, KX, pY0, 1024, HDIM, HDIM);

    for (int t = 0; t < 3; t++) {
        colsum_kernel<<<CH_BLOCKS, 256>>>();
        msprop_kernel<<<CH_BLOCKS, 256>>>(matrix);
        hbar_kernel<<<NH_BLOCKS, 256>>>();
        ms_split_kernel<<<(DPAD * 1024) / 256, 256>>>();
        /* YS = MScat @ Wcat[:, :1024]^T — fp16x3 full corrections */
        gemm3<<<dim3(KX / GBN, DPAD / GBM), 256, GEMM_SMEM>>>(
            pMSh, pMSl, 1024, pWch, pWcl, KX, pYS, KX, 1024, 1024);
        /* Z1 = Hbar @ Wcat[:, 0:512]^T ; Z2 = Hbar @ Wcat[:, 512:1024]^T */
        gemm3<<<dim3(KX / GBN, N_OBJ / GBM), 256, GEMM_SMEM>>>(
            pHbh, pHbl, HDIM, pWch, pWcl, KX, pZ1, KX, HDIM, HDIM);
        gemm3<<<dim3(KX / GBN, N_OBJ / GBM), 256, GEMM_SMEM>>>(
            pHbh, pHbl, HDIM, pWch + 512, pWcl + 512, KX, pZ2, KX, HDIM, HDIM);
        if (t > 0) {
            /* transpose (hidden - hbar) -> Hdt, then MMA propagation */
            hdt_kernel<<<dim3(HDIM / HT_HB, N_OBJ), 256>>>();
            prop_mma<<<dim3(HDIM / PM_H, (C_CLS + PM_D - 1) / PM_D, N_OBJ),
                       128, PM_SMEM>>>();
            /* Yres[:, 0:1024] = X @ Wcat[0:1024]^T : hi-only lean, K=1536 */
            gemm1<<<dim3(1024 / GBN, NCROW / GBM), 256, GEMM1_SMEM>>>(
                pXh, KX, pWch, KX, pY, KX, KX);
            /* Yres[:, 1024:1536]: Wcat rows 1024.. zero for k>=1024 -> K=1024 */
            gemm1<<<dim3(512 / GBN, NCROW / GBM), 256, GEMM1_SMEM>>>(
                pXh, KX, pWch + (size_t)1024 * KX, KX, pY + 1024, KX, 1024);
        }
        pw_rv<<<PW_BLOCKS, 256>>>(b4w, b4u, t == 0 ? 1 : 0);
        /* U5 = (rv*h) @ W5u^T : hi-only lean */
        gemm1<<<dim3(HDIM / GBN, NCROW / GBM), 256, GEMM1_SMEM>>>(
            pRHh, HDIM, pW5uh, HDIM, pU5, HDIM, HDIM);
        pw_update<<<PW_BLOCKS, 256>>>(b3w, b3u, b5w, b5u, t == 0 ? 1 : 0);
    }

    /* O1 = hidden @ Wo1^T — full corrections (classifier-facing) */
    gemm3<<<dim3(HDIM / GBN, NCROW / GBM), 256, GEMM_SMEM>>>(
        pHh, pHl, HDIM, pWoh, pWol, 2 * HDIM, pO1, HDIM, HDIM, HDIM);
    pw_relu<<<PW_BLOCKS, 256>>>(bout);

    cls_partial<<<dim3(N_OBJ / 32, C_CLS), 160>>>(wcls);
    cls_reduce<<<(N_OBJ * C_CLS + 255) / 256, 256>>>(bcls, out);
}